// round 11
// baseline (speedup 1.0000x reference)
#include <cuda_runtime.h>
#include <cuda_bf16.h>
#include <math.h>
#include <stdint.h>

// Problem constants
#define BATCH 8
#define NPTS 256
#define HD 128
#define BN (BATCH*NPTS)           // 2048 rows
#define BSTRIDE 136               // padded row stride (bf16) for ldmatrix
#define ROWB (BSTRIDE*2)          // 272 bytes per row
#define JT 64                     // j-tile rows
#define NTILES (NPTS/JT)          // 4
#define ATH_BYTES (JT*ROWB)       // 17408 per A half (hi or lo)
#define ABUF_BYTES (2*ATH_BYTES)  // 34816 per A buffer (hi+lo)
#define BT_HALF (128*ROWB)        // 34816 per B half
#define OFF_B_HI (2*ABUF_BYTES)   // 69632
#define OFF_B_LO (OFF_B_HI + BT_HALF)  // 104448
#define OFF_EXT  (OFF_B_LO + BT_HALF)  // 139264
#define E_SMEM_TOTAL (OFF_EXT + 1280*4)
#define C_SMEM_TOTAL (OFF_EXT + 784*4)

// named barrier ids: full0=1 full1=2 empty0=3 empty1=4
#define BAR_SYNC(id)   asm volatile("bar.sync %0, 256;"   :: "r"(id) : "memory")
#define BAR_ARRIVE(id) asm volatile("bar.arrive %0, 256;" :: "r"(id) : "memory")

// ---------------- scratch (device globals; no allocation allowed) ----------
__device__ float g_PA[BN*HD];
__device__ float g_PB[BN*HD];
__device__ float g_CA[BN*HD];
__device__ float g_CB[BN*HD];
__device__ float g_D2[BN*NPTS];
__device__ float g_D02[BN*NPTS];
__device__ float g_agg[BN*HD];
__device__ float g_upd[BN*3];
__device__ __align__(16) __nv_bfloat16 g_eBhi[128*BSTRIDE];
__device__ __align__(16) __nv_bfloat16 g_eBlo[128*BSTRIDE];
__device__ __align__(16) __nv_bfloat16 g_cBhi[128*BSTRIDE];
__device__ __align__(16) __nv_bfloat16 g_cBlo[128*BSTRIDE];

// precise sigmoid (gates only)
__device__ __forceinline__ float sigm(float v) {
    return __fdividef(1.f, 1.f + __expf(-v));
}
__device__ __forceinline__ float siluf(float v) {
    return v * sigm(v);
}
// fast silu: 1 MUFU (tanh.approx); R8/R10 measured rel_err impact: none.
__device__ __forceinline__ float silu_fast(float v) {
    float h = 0.5f * v;
    float t;
    asm("tanh.approx.f32 %0, %1;" : "=f"(t) : "f"(h));
    return fmaf(h, t, h);
}

__device__ __forceinline__ uint32_t smem_u32(const void* p) {
    uint32_t a;
    asm("{ .reg .u64 tmp; cvta.to.shared.u64 tmp, %1; cvt.u32.u64 %0, tmp; }"
        : "=r"(a) : "l"(p));
    return a;
}

__device__ __forceinline__ void ldsm4(uint32_t r[4], uint32_t addr) {
    asm volatile("ldmatrix.sync.aligned.m8n8.x4.shared.b16 {%0,%1,%2,%3}, [%4];"
        : "=r"(r[0]), "=r"(r[1]), "=r"(r[2]), "=r"(r[3]) : "r"(addr));
}

__device__ __forceinline__ void mma_bf16(float d[4], const uint32_t a[4],
                                         const uint32_t b0, const uint32_t b1) {
    asm volatile(
        "mma.sync.aligned.m16n8k16.row.col.f32.bf16.bf16.f32 "
        "{%0,%1,%2,%3}, {%4,%5,%6,%7}, {%8,%9}, {%0,%1,%2,%3};"
        : "+f"(d[0]), "+f"(d[1]), "+f"(d[2]), "+f"(d[3])
        : "r"(a[0]), "r"(a[1]), "r"(a[2]), "r"(a[3]), "r"(b0), "r"(b1));
}

// ---------------- kernel 0: prep W2^T hi/lo padded tiles -------------------
__global__ void __launch_bounds__(128) prep_kernel(
    const float* __restrict__ e2w, const float* __restrict__ c2w)
{
    int n = blockIdx.x;
    int k = threadIdx.x;
    int idx = n * BSTRIDE + k;
    float v = e2w[k * HD + n];
    __nv_bfloat16 h = __float2bfloat16(v);
    g_eBhi[idx] = h;
    g_eBlo[idx] = __float2bfloat16(v - __bfloat162float(h));
    v = c2w[k * HD + n];
    h = __float2bfloat16(v);
    g_cBhi[idx] = h;
    g_cBlo[idx] = __float2bfloat16(v - __bfloat162float(h));
}

// ---------------- kernel 1: per-node projections ---------------------------
__global__ void __launch_bounds__(128) proj_kernel(
    const float* __restrict__ h,
    const float* __restrict__ e1w,
    const float* __restrict__ c1w)
{
    const int r0 = blockIdx.x * 8;
    const int t  = threadIdx.x;
    __shared__ float hs[8][HD];
    #pragma unroll
    for (int r = 0; r < 8; r++) hs[r][t] = h[(r0 + r) * HD + t];
    __syncthreads();

    float pa[8], pb[8], ca[8], cb[8];
    #pragma unroll
    for (int r = 0; r < 8; r++) { pa[r]=0.f; pb[r]=0.f; ca[r]=0.f; cb[r]=0.f; }

    for (int k = 0; k < HD; k++) {
        float wea = e1w[k * HD + t];
        float web = e1w[(HD + k) * HD + t];
        float wca = c1w[k * HD + t];
        float wcb = c1w[(HD + k) * HD + t];
        #pragma unroll
        for (int r = 0; r < 8; r++) {
            float hk = hs[r][k];
            pa[r] = fmaf(hk, wea, pa[r]);
            pb[r] = fmaf(hk, web, pb[r]);
            ca[r] = fmaf(hk, wca, ca[r]);
            cb[r] = fmaf(hk, wcb, cb[r]);
        }
    }
    #pragma unroll
    for (int r = 0; r < 8; r++) {
        int bi = r0 + r;
        g_PA[bi * HD + t] = pa[r];
        g_PB[bi * HD + t] = pb[r];
        g_CA[bi * HD + t] = ca[r];
        g_CB[bi * HD + t] = cb[r];
    }
}

// ---------------- kernel 2: pairwise squared distances ---------------------
__global__ void __launch_bounds__(256) dist_kernel(
    const float* __restrict__ x, const float* __restrict__ x0)
{
    int idx = blockIdx.x * 256 + threadIdx.x;
    int j = idx & 255;
    int bi = idx >> 8;
    int b  = bi >> 8;
    const float* xi = x  + bi * 3;
    const float* xj = x  + (b * NPTS + j) * 3;
    float dx = xi[0]-xj[0], dy = xi[1]-xj[1], dz = xi[2]-xj[2];
    g_D2[idx] = dx*dx + dy*dy + dz*dz;
    const float* yi = x0 + bi * 3;
    const float* yj = x0 + (b * NPTS + j) * 3;
    float ex = yi[0]-yj[0], ey = yi[1]-yj[1], ez = yi[2]-yj[2];
    g_D02[idx] = ex*ex + ey*ey + ez*ez;
}

// producer: warp p covers tile rows p*16..p*16+15; lane -> k = lane*4..+3.
__device__ __forceinline__ void produce_tile16(
    int p, int lane, int j0,
    const float4 pab, const float4 w256_4, const float4 w257_4,
    const float* __restrict__ Pbase,
    const float* d2all, const float* d02all,
    uint32_t aBuf)
{
    #pragma unroll 4
    for (int rr = 0; rr < 16; rr++) {
        int row = p * 16 + rr;
        const float4 pb4 = *reinterpret_cast<const float4*>(
            &Pbase[(size_t)(j0 + row) * HD + lane * 4]);
        float dj = d2all[j0 + row], d0j = d02all[j0 + row];
        float v0 = silu_fast(pab.x + pb4.x + dj * w256_4.x + d0j * w257_4.x);
        float v1 = silu_fast(pab.y + pb4.y + dj * w256_4.y + d0j * w257_4.y);
        float v2 = silu_fast(pab.z + pb4.z + dj * w256_4.z + d0j * w257_4.z);
        float v3 = silu_fast(pab.w + pb4.w + dj * w256_4.w + d0j * w257_4.w);
        __nv_bfloat16 h0 = __float2bfloat16(v0);
        __nv_bfloat16 h1 = __float2bfloat16(v1);
        __nv_bfloat16 h2 = __float2bfloat16(v2);
        __nv_bfloat16 h3 = __float2bfloat16(v3);
        __nv_bfloat162 H01 = __halves2bfloat162(h0, h1);
        __nv_bfloat162 H23 = __halves2bfloat162(h2, h3);
        __nv_bfloat162 L01 = __halves2bfloat162(
            __float2bfloat16(v0 - __bfloat162float(h0)),
            __float2bfloat16(v1 - __bfloat162float(h1)));
        __nv_bfloat162 L23 = __halves2bfloat162(
            __float2bfloat16(v2 - __bfloat162float(h2)),
            __float2bfloat16(v3 - __bfloat162float(h3)));
        uint32_t off = row * ROWB + lane * 8;
        asm volatile("st.shared.v2.b32 [%0], {%1, %2};"
            :: "r"(aBuf + off),
               "r"(*reinterpret_cast<uint32_t*>(&H01)),
               "r"(*reinterpret_cast<uint32_t*>(&H23)) : "memory");
        asm volatile("st.shared.v2.b32 [%0], {%1, %2};"
            :: "r"(aBuf + ATH_BYTES + off),
               "r"(*reinterpret_cast<uint32_t*>(&L01)),
               "r"(*reinterpret_cast<uint32_t*>(&L23)) : "memory");
    }
}

// consumer GEMM: warp tile 16 rows x 128 cols; 3-pass bf16 split.
__device__ __forceinline__ void consumer_gemm(
    float acc[16][4], uint32_t aBuf, uint32_t aoff, uint32_t bcom,
    uint32_t bHi32, uint32_t bLo32)
{
    for (int ks = 0; ks < 8; ks++) {
        const uint32_t kb = ks * 32;
        uint32_t ah[4], al[4];
        ldsm4(ah, aBuf + aoff + kb);
        ldsm4(al, aBuf + ATH_BYTES + aoff + kb);
        #pragma unroll
        for (int nb = 0; nb < 8; nb++) {
            uint32_t bh[4], bl[4];
            uint32_t baddr = nb * (16 * ROWB) + bcom + kb;
            ldsm4(bh, bHi32 + baddr);
            ldsm4(bl, bLo32 + baddr);
            mma_bf16(acc[2*nb],     ah, bh[0], bh[1]);
            mma_bf16(acc[2*nb + 1], ah, bh[2], bh[3]);
            mma_bf16(acc[2*nb],     ah, bl[0], bl[1]);
            mma_bf16(acc[2*nb + 1], ah, bl[2], bl[3]);
            mma_bf16(acc[2*nb],     al, bh[0], bh[1]);
            mma_bf16(acc[2*nb + 1], al, bh[2], bh[3]);
        }
    }
}

// ---------------- kernel 3: edge chain -> g_agg ----------------------------
// ext floats: d2all[256] d02all[256] b2s[128] eiws[128] aggW[512]
__global__ void __launch_bounds__(256) edge_kernel(
    const float* __restrict__ e1w, const float* __restrict__ e1b,
    const float* __restrict__ e2b,
    const float* __restrict__ eiw, const float* __restrict__ eib)
{
    extern __shared__ __align__(16) unsigned char smem[];
    float* ext    = (float*)(smem + OFF_EXT);
    float* d2all  = ext;         float* d02all = ext + 256;
    float* b2s    = ext + 512;   float* eiws   = ext + 640;
    float* aggW   = ext + 768;   // 4 warps x 128 cols

    const uint32_t smem32 = smem_u32(smem);
    const uint32_t bHi32 = smem32 + OFF_B_HI, bLo32 = smem32 + OFF_B_LO;

    const int bi = blockIdx.x;
    const int b  = bi >> 8;
    const int i  = bi & 255;
    const int t  = threadIdx.x;
    const int lane = t & 31, w = t >> 5;

    // prologue (all threads)
    {
        const uint4* srcH = (const uint4*)g_eBhi;
        const uint4* srcL = (const uint4*)g_eBlo;
        uint4* dstH = (uint4*)(smem + OFF_B_HI);
        uint4* dstL = (uint4*)(smem + OFF_B_LO);
        for (int idx = t; idx < BT_HALF/16; idx += 256) {
            dstH[idx] = srcH[idx];
            dstL[idx] = srcL[idx];
        }
    }
    if (t < 128) { b2s[t] = e2b[t]; eiws[t] = eiw[t]; }
    d2all[t]  = g_D2 [bi * NPTS + t];
    d02all[t] = g_D02[bi * NPTS + t];
    __syncthreads();

    if (w >= 4) {
        // ---- producer warps (SMSP 0-3) ----
        const int p  = w - 4;
        const int k0 = lane * 4;
        float4 pab = *reinterpret_cast<const float4*>(&g_PA[bi * HD + k0]);
        const float4 b1_4 = *reinterpret_cast<const float4*>(&e1b[k0]);
        pab.x += b1_4.x; pab.y += b1_4.y; pab.z += b1_4.z; pab.w += b1_4.w;
        const float4 w256_4 = *reinterpret_cast<const float4*>(&e1w[256*HD + k0]);
        const float4 w257_4 = *reinterpret_cast<const float4*>(&e1w[257*HD + k0]);
        const float* PBb = g_PB + (size_t)b * NPTS * HD;
        for (int tile = 0; tile < NTILES; tile++) {
            if (tile >= 2) BAR_SYNC(3 + (tile & 1));
            produce_tile16(p, lane, tile * JT, pab, w256_4, w257_4,
                           PBb, d2all, d02all,
                           smem32 + (tile & 1) * ABUF_BYTES);
            BAR_ARRIVE(1 + (tile & 1));
        }
    } else {
        // ---- consumer warps (SMSP 0-3): 16 rows x 128 cols each ----
        const int s = lane & 3, q = lane >> 2;
        const int mrow0 = w * 16;
        const uint32_t aoff = (mrow0 + (lane & 15)) * ROWB + (lane >> 4) * 16;
        const uint32_t bcom = ((lane & 7) + ((lane >> 4) & 1) * 8) * ROWB
                            + ((lane >> 3) & 1) * 16;
        const float bi0 = eib[0];

        float aggacc[32];
        #pragma unroll
        for (int c = 0; c < 32; c++) aggacc[c] = 0.f;

        for (int tile = 0; tile < NTILES; tile++) {
            BAR_SYNC(1 + (tile & 1));
            const uint32_t aBuf = smem32 + (tile & 1) * ABUF_BYTES;
            float acc[16][4];
            #pragma unroll
            for (int a = 0; a < 16; a++)
                #pragma unroll
                for (int e = 0; e < 4; e++) acc[a][e] = 0.f;
            consumer_gemm(acc, aBuf, aoff, bcom, bHi32, bLo32);
            BAR_ARRIVE(3 + (tile & 1));

            // epilogue: m = silu(D+b2), in-warp row dots, gate, agg (regs only)
            float dot0 = 0.f, dot1 = 0.f;
            #pragma unroll
            for (int ni = 0; ni < 16; ni++) {
                int c0 = ni * 8 + 2 * s;
                float2 b2v  = *reinterpret_cast<const float2*>(&b2s[c0]);
                float2 eiv  = *reinterpret_cast<const float2*>(&eiws[c0]);
                float* A = acc[ni];
                A[0] = silu_fast(A[0] + b2v.x); A[1] = silu_fast(A[1] + b2v.y);
                A[2] = silu_fast(A[2] + b2v.x); A[3] = silu_fast(A[3] + b2v.y);
                dot0 += A[0]*eiv.x + A[1]*eiv.y;
                dot1 += A[2]*eiv.x + A[3]*eiv.y;
            }
            dot0 += __shfl_xor_sync(0xffffffffu, dot0, 1);
            dot0 += __shfl_xor_sync(0xffffffffu, dot0, 2);
            dot1 += __shfl_xor_sync(0xffffffffu, dot1, 1);
            dot1 += __shfl_xor_sync(0xffffffffu, dot1, 2);
            int jrow = tile * JT + mrow0 + q;
            float e0 = sigm(dot0 + bi0);
            float e1 = sigm(dot1 + bi0);
            if (jrow == i)     e0 = 0.f;
            if (jrow + 8 == i) e1 = 0.f;
            #pragma unroll
            for (int ni = 0; ni < 16; ni++) {
                float* A = acc[ni];
                aggacc[2*ni]   = fmaf(e0, A[0], fmaf(e1, A[2], aggacc[2*ni]));
                aggacc[2*ni+1] = fmaf(e0, A[1], fmaf(e1, A[3], aggacc[2*ni+1]));
            }
        }
        // reduce over q-lanes (cols depend only on s)
        #pragma unroll
        for (int c = 0; c < 32; c++) {
            float v = aggacc[c];
            v += __shfl_xor_sync(0xffffffffu, v, 4);
            v += __shfl_xor_sync(0xffffffffu, v, 8);
            v += __shfl_xor_sync(0xffffffffu, v, 16);
            aggacc[c] = v;
        }
        if (q == 0) {
            #pragma unroll
            for (int ni = 0; ni < 16; ni++) {
                aggW[w * 128 + ni * 8 + 2 * s]     = aggacc[2*ni];
                aggW[w * 128 + ni * 8 + 2 * s + 1] = aggacc[2*ni+1];
            }
        }
    }
    __syncthreads();
    if (t < 128) {
        float sv = aggW[t] + aggW[128 + t] + aggW[256 + t] + aggW[384 + t];
        g_agg[bi * HD + t] = sv * (1.0f / 256.0f);
    }
}

// ---------------- kernel 4: coordinate chain -> g_upd ----------------------
// ext floats: d2all[256] d02all[256] b2s[128] c3ws[128] updW[12]
__global__ void __launch_bounds__(256) cor_kernel(
    const float* __restrict__ c1w, const float* __restrict__ c1b,
    const float* __restrict__ c2b,
    const float* __restrict__ c3w, const float* __restrict__ c3b,
    const float* __restrict__ x)
{
    extern __shared__ __align__(16) unsigned char smem[];
    float* ext    = (float*)(smem + OFF_EXT);
    float* d2all  = ext;         float* d02all = ext + 256;
    float* b2s    = ext + 512;   float* c3ws   = ext + 640;
    float* updW   = ext + 768;   // 4 warps x 3

    const uint32_t smem32 = smem_u32(smem);
    const uint32_t bHi32 = smem32 + OFF_B_HI, bLo32 = smem32 + OFF_B_LO;

    const int bi = blockIdx.x;
    const int b  = bi >> 8;
    const int i  = bi & 255;
    const int t  = threadIdx.x;
    const int lane = t & 31, w = t >> 5;

    {
        const uint4* srcH = (const uint4*)g_cBhi;
        const uint4* srcL = (const uint4*)g_cBlo;
        uint4* dstH = (uint4*)(smem + OFF_B_HI);
        uint4* dstL = (uint4*)(smem + OFF_B_LO);
        for (int idx = t; idx < BT_HALF/16; idx += 256) {
            dstH[idx] = srcH[idx];
            dstL[idx] = srcL[idx];
        }
    }
    if (t < 128) { b2s[t] = c2b[t]; c3ws[t] = c3w[t]; }
    d2all[t]  = g_D2 [bi * NPTS + t];
    d02all[t] = g_D02[bi * NPTS + t];
    __syncthreads();

    if (w >= 4) {
        const int p  = w - 4;
        const int k0 = lane * 4;
        float4 pab = *reinterpret_cast<const float4*>(&g_CA[bi * HD + k0]);
        const float4 b1_4 = *reinterpret_cast<const float4*>(&c1b[k0]);
        pab.x += b1_4.x; pab.y += b1_4.y; pab.z += b1_4.z; pab.w += b1_4.w;
        const float4 w256_4 = *reinterpret_cast<const float4*>(&c1w[256*HD + k0]);
        const float4 w257_4 = *reinterpret_cast<const float4*>(&c1w[257*HD + k0]);
        const float* CBb = g_CB + (size_t)b * NPTS * HD;
        for (int tile = 0; tile < NTILES; tile++) {
            if (tile >= 2) BAR_SYNC(3 + (tile & 1));
            produce_tile16(p, lane, tile * JT, pab, w256_4, w257_4,
                           CBb, d2all, d02all,
                           smem32 + (tile & 1) * ABUF_BYTES);
            BAR_ARRIVE(1 + (tile & 1));
        }
    } else {
        const int s = lane & 3, q = lane >> 2;
        const int mrow0 = w * 16;
        const uint32_t aoff = (mrow0 + (lane & 15)) * ROWB + (lane >> 4) * 16;
        const uint32_t bcom = ((lane & 7) + ((lane >> 4) & 1) * 8) * ROWB
                            + ((lane >> 3) & 1) * 16;
        const float b3 = c3b[0];
        const float xi0 = x[bi * 3 + 0];
        const float xi1 = x[bi * 3 + 1];
        const float xi2 = x[bi * 3 + 2];
        float ux = 0.f, uy = 0.f, uz = 0.f;

        for (int tile = 0; tile < NTILES; tile++) {
            BAR_SYNC(1 + (tile & 1));
            const uint32_t aBuf = smem32 + (tile & 1) * ABUF_BYTES;
            float acc[16][4];
            #pragma unroll
            for (int a = 0; a < 16; a++)
                #pragma unroll
                for (int e = 0; e < 4; e++) acc[a][e] = 0.f;
            consumer_gemm(acc, aBuf, aoff, bcom, bHi32, bLo32);
            BAR_ARRIVE(3 + (tile & 1));

            float dot0 = 0.f, dot1 = 0.f;
            #pragma unroll
            for (int ni = 0; ni < 16; ni++) {
                int c0 = ni * 8 + 2 * s;
                float2 b2v = *reinterpret_cast<const float2*>(&b2s[c0]);
                float2 c3v = *reinterpret_cast<const float2*>(&c3ws[c0]);
                float* A = acc[ni];
                float m0 = silu_fast(A[0] + b2v.x), m1 = silu_fast(A[1] + b2v.y);
                float m2 = silu_fast(A[2] + b2v.x), m3 = silu_fast(A[3] + b2v.y);
                dot0 += m0*c3v.x + m1*c3v.y;
                dot1 += m2*c3v.x + m3*c3v.y;
            }
            dot0 += __shfl_xor_sync(0xffffffffu, dot0, 1);
            dot0 += __shfl_xor_sync(0xffffffffu, dot0, 2);
            dot1 += __shfl_xor_sync(0xffffffffu, dot1, 1);
            dot1 += __shfl_xor_sync(0xffffffffu, dot1, 2);
            if (s == 0) {
                int j0r = tile * JT + mrow0 + q;
                #pragma unroll
                for (int half = 0; half < 2; half++) {
                    int j = j0r + half * 8;
                    float dt = (half == 0) ? dot0 : dot1;
                    if (j != i) {
                        float cw = dt + b3;
                        float d2v = d2all[j];
                        float dist = (d2v > 0.f) ? sqrtf(d2v) : 0.f;
                        float f = __fdividef(cw, dist + 1.f);
                        const float* xj = x + ((size_t)b * NPTS + j) * 3;
                        ux = fmaf(f, xi0 - xj[0], ux);
                        uy = fmaf(f, xi1 - xj[1], uy);
                        uz = fmaf(f, xi2 - xj[2], uz);
                    }
                }
            }
        }
        // reduce over q (s==0 lanes hold data; others zero)
        ux += __shfl_xor_sync(0xffffffffu, ux, 4);
        ux += __shfl_xor_sync(0xffffffffu, ux, 8);
        ux += __shfl_xor_sync(0xffffffffu, ux, 16);
        uy += __shfl_xor_sync(0xffffffffu, uy, 4);
        uy += __shfl_xor_sync(0xffffffffu, uy, 8);
        uy += __shfl_xor_sync(0xffffffffu, uy, 16);
        uz += __shfl_xor_sync(0xffffffffu, uz, 4);
        uz += __shfl_xor_sync(0xffffffffu, uz, 8);
        uz += __shfl_xor_sync(0xffffffffu, uz, 16);
        if (lane == 0) {
            updW[w * 3 + 0] = ux;
            updW[w * 3 + 1] = uy;
            updW[w * 3 + 2] = uz;
        }
    }
    __syncthreads();
    if (t < 3) {
        float sv = updW[t] + updW[3 + t] + updW[6 + t] + updW[9 + t];
        g_upd[bi * 3 + t] = sv * (1.0f / 256.0f);
    }
}

// ---------------- kernel 5: node MLP + outputs -----------------------------
__global__ void __launch_bounds__(128) final_kernel(
    const float* __restrict__ hin, const float* __restrict__ xin,
    const float* __restrict__ pm,
    const float* __restrict__ n1w, const float* __restrict__ n1b,
    const float* __restrict__ n2w, const float* __restrict__ n2b,
    float* __restrict__ out)
{
    const int r0 = blockIdx.x * 8;
    const int t  = threadIdx.x;
    __shared__ float nin[8][256];
    __shared__ float tmid[8][HD];
    #pragma unroll
    for (int r = 0; r < 8; r++) {
        nin[r][t]       = hin[(r0 + r) * HD + t];
        nin[r][HD + t]  = g_agg[(r0 + r) * HD + t];
    }
    __syncthreads();
    float a[8];
    #pragma unroll
    for (int r = 0; r < 8; r++) a[r] = n1b[t];
    for (int k = 0; k < 256; k++) {
        float wv = n1w[k * HD + t];
        #pragma unroll
        for (int r = 0; r < 8; r++) a[r] = fmaf(nin[r][k], wv, a[r]);
    }
    #pragma unroll
    for (int r = 0; r < 8; r++) tmid[r][t] = siluf(a[r]);
    __syncthreads();
    #pragma unroll
    for (int r = 0; r < 8; r++) a[r] = n2b[t];
    for (int k = 0; k < HD; k++) {
        float wv = n2w[k * HD + t];
        #pragma unroll
        for (int r = 0; r < 8; r++) a[r] = fmaf(tmid[r][k], wv, a[r]);
    }
    float* outx = out;                  // x_next: BN*3
    float* outh = out + BN * 3;         // h_next: BN*HD
    #pragma unroll
    for (int r = 0; r < 8; r++) {
        int bi = r0 + r;
        float mask = pm[bi];
        outh[bi * HD + t] = (nin[r][t] + a[r]) * mask;
        if (t < 3) outx[bi * 3 + t] = (xin[bi * 3 + t] + g_upd[bi * 3 + t]) * mask;
    }
}

// ---------------- launch ----------------------------------------------------
extern "C" void kernel_launch(void* const* d_in, const int* in_sizes, int n_in,
                              void* d_out, int out_size)
{
    const float* x   = (const float*)d_in[0];
    const float* h   = (const float*)d_in[1];
    const float* x0  = (const float*)d_in[2];
    const float* pm  = (const float*)d_in[3];
    const float* e1w = (const float*)d_in[4];
    const float* e1b = (const float*)d_in[5];
    const float* e2w = (const float*)d_in[6];
    const float* e2b = (const float*)d_in[7];
    const float* eiw = (const float*)d_in[8];
    const float* eib = (const float*)d_in[9];
    const float* n1w = (const float*)d_in[10];
    const float* n1b = (const float*)d_in[11];
    const float* n2w = (const float*)d_in[12];
    const float* n2b = (const float*)d_in[13];
    const float* c1w = (const float*)d_in[14];
    const float* c1b = (const float*)d_in[15];
    const float* c2w = (const float*)d_in[16];
    const float* c2b = (const float*)d_in[17];
    const float* c3w = (const float*)d_in[18];
    const float* c3b = (const float*)d_in[19];
    float* out = (float*)d_out;

    cudaFuncSetAttribute(edge_kernel,
        cudaFuncAttributeMaxDynamicSharedMemorySize, E_SMEM_TOTAL);
    cudaFuncSetAttribute(cor_kernel,
        cudaFuncAttributeMaxDynamicSharedMemorySize, C_SMEM_TOTAL);

    prep_kernel<<<128, 128>>>(e2w, c2w);
    proj_kernel<<<BN / 8, 128>>>(h, e1w, c1w);
    dist_kernel<<<(BN * NPTS) / 256, 256>>>(x, x0);
    edge_kernel<<<BN, 256, E_SMEM_TOTAL>>>(e1w, e1b, e2b, eiw, eib);
    cor_kernel<<<BN, 256, C_SMEM_TOTAL>>>(c1w, c1b, c2b, c3w, c3b, x);
    final_kernel<<<BN / 8, 128>>>(h, x, pm, n1w, n1b, n2w, n2b, out);
}

// round 12
// speedup vs baseline: 1.5592x; 1.5592x over previous
#include <cuda_runtime.h>
#include <cuda_fp16.h>
#include <math.h>
#include <stdint.h>

// Problem constants
#define BATCH 8
#define NPTS 256
#define HD 128
#define BN (BATCH*NPTS)          // 2048 rows
#define BSTRIDE 136              // padded row stride (fp16 elems) for ldmatrix
#define ROWB (BSTRIDE*2)         // 272 bytes per row
#define JT 32                    // j-tile rows
#define BT_HALF (128*ROWB)       // 34816 : B tile (fp16, single precision level)
#define ATH_BYTES (JT*ROWB)      // 8704 per A half (hi or lo)
#define ABUF_BYTES (2*ATH_BYTES) // 17408 per A buffer (hi+lo)

// ---------------- scratch (device globals; no allocation allowed) ----------
__device__ float g_PA[BN*HD];
__device__ float g_PB[BN*HD];
__device__ float g_CA[BN*HD];
__device__ float g_CB[BN*HD];
__device__ float g_D2[BN*NPTS];
__device__ float g_D02[BN*NPTS];
__device__ float g_agg[BN*HD];
__device__ float g_upd[BN*3];
// W2^T in padded [n][k] fp16 layout (prep_kernel fills)
__device__ __align__(16) __half g_eBh[128*BSTRIDE];
__device__ __align__(16) __half g_cBh[128*BSTRIDE];

// precise sigmoid (gates only)
__device__ __forceinline__ float sigm(float v) {
    return __fdividef(1.f, 1.f + __expf(-v));
}
__device__ __forceinline__ float siluf(float v) {
    return v * sigm(v);
}
// fast silu: 1 MUFU (tanh.approx); R10 measured: no rel_err impact.
__device__ __forceinline__ float silu_fast(float v) {
    float h = 0.5f * v;
    float t;
    asm("tanh.approx.f32 %0, %1;" : "=f"(t) : "f"(h));
    return fmaf(h, t, h);
}

__device__ __forceinline__ uint32_t smem_u32(const void* p) {
    uint32_t a;
    asm("{ .reg .u64 tmp; cvta.to.shared.u64 tmp, %1; cvt.u32.u64 %0, tmp; }"
        : "=r"(a) : "l"(p));
    return a;
}

__device__ __forceinline__ void ldsm4(uint32_t r[4], uint32_t addr) {
    asm volatile("ldmatrix.sync.aligned.m8n8.x4.shared.b16 {%0,%1,%2,%3}, [%4];"
        : "=r"(r[0]), "=r"(r[1]), "=r"(r[2]), "=r"(r[3]) : "r"(addr));
}

__device__ __forceinline__ void mma_f16(float d[4], const uint32_t a[4],
                                        const uint32_t b0, const uint32_t b1) {
    asm volatile(
        "mma.sync.aligned.m16n8k16.row.col.f32.f16.f16.f32 "
        "{%0,%1,%2,%3}, {%4,%5,%6,%7}, {%8,%9}, {%0,%1,%2,%3};"
        : "+f"(d[0]), "+f"(d[1]), "+f"(d[2]), "+f"(d[3])
        : "r"(a[0]), "r"(a[1]), "r"(a[2]), "r"(a[3]), "r"(b0), "r"(b1));
}

// ---------------- kernel 0: prep W2^T fp16 padded tiles --------------------
__global__ void __launch_bounds__(128) prep_kernel(
    const float* __restrict__ e2w, const float* __restrict__ c2w)
{
    int n = blockIdx.x;
    int k = threadIdx.x;
    int idx = n * BSTRIDE + k;
    g_eBh[idx] = __float2half_rn(e2w[k * HD + n]);
    g_cBh[idx] = __float2half_rn(c2w[k * HD + n]);
}

// ---------------- kernel 1: per-node projections ---------------------------
__global__ void __launch_bounds__(128) proj_kernel(
    const float* __restrict__ h,
    const float* __restrict__ e1w,
    const float* __restrict__ c1w)
{
    const int r0 = blockIdx.x * 8;
    const int t  = threadIdx.x;
    __shared__ float hs[8][HD];
    #pragma unroll
    for (int r = 0; r < 8; r++) hs[r][t] = h[(r0 + r) * HD + t];
    __syncthreads();

    float pa[8], pb[8], ca[8], cb[8];
    #pragma unroll
    for (int r = 0; r < 8; r++) { pa[r]=0.f; pb[r]=0.f; ca[r]=0.f; cb[r]=0.f; }

    for (int k = 0; k < HD; k++) {
        float wea = e1w[k * HD + t];
        float web = e1w[(HD + k) * HD + t];
        float wca = c1w[k * HD + t];
        float wcb = c1w[(HD + k) * HD + t];
        #pragma unroll
        for (int r = 0; r < 8; r++) {
            float hk = hs[r][k];
            pa[r] = fmaf(hk, wea, pa[r]);
            pb[r] = fmaf(hk, web, pb[r]);
            ca[r] = fmaf(hk, wca, ca[r]);
            cb[r] = fmaf(hk, wcb, cb[r]);
        }
    }
    #pragma unroll
    for (int r = 0; r < 8; r++) {
        int bi = r0 + r;
        g_PA[bi * HD + t] = pa[r];
        g_PB[bi * HD + t] = pb[r];
        g_CA[bi * HD + t] = ca[r];
        g_CB[bi * HD + t] = cb[r];
    }
}

// ---------------- kernel 2: pairwise squared distances ---------------------
__global__ void __launch_bounds__(256) dist_kernel(
    const float* __restrict__ x, const float* __restrict__ x0)
{
    int idx = blockIdx.x * 256 + threadIdx.x;
    int j = idx & 255;
    int bi = idx >> 8;
    int b  = bi >> 8;
    const float* xi = x  + bi * 3;
    const float* xj = x  + (b * NPTS + j) * 3;
    float dx = xi[0]-xj[0], dy = xi[1]-xj[1], dz = xi[2]-xj[2];
    g_D2[idx] = dx*dx + dy*dy + dz*dz;
    const float* yi = x0 + bi * 3;
    const float* yj = x0 + (b * NPTS + j) * 3;
    float ex = yi[0]-yj[0], ey = yi[1]-yj[1], ez = yi[2]-yj[2];
    g_D02[idx] = ex*ex + ey*ey + ez*ez;
}

// ============================================================================
// smem layout (bytes):
//   [0      : 17408)   A buffer 0 (hi 8704 | lo 8704)   32 x 136 fp16 each
//   [17408  : 34816)   A buffer 1 (hi | lo)
//   [34816  : 69632)   B tile (128 x 136 fp16)
//   [69632  : ...)     ext float scratch
// ============================================================================
#define OFF_BH   34816
#define OFF_EXT  69632
#define E_SMEM_TOTAL (OFF_EXT + 1184*4)
#define C_SMEM_TOTAL (OFF_EXT + 992*4)

// producer: warp w -> local rows w*4..w*4+3; lane -> k = lane*4..lane*4+3.
// fp16 hi/lo split: A = Ah + Al exact to 2^-22.
__device__ __forceinline__ void produce_tile(
    int w, int lane, int j0,
    const float4 pab, const float4 w256_4, const float4 w257_4,
    const float* __restrict__ Pbase,
    const float* d2all, const float* d02all,
    uint32_t aBuf)
{
    const int k0 = lane * 4;
    #pragma unroll
    for (int rr = 0; rr < 4; rr++) {
        int row = w * 4 + rr;
        const float4 pb4 = *reinterpret_cast<const float4*>(
            &Pbase[(size_t)(j0 + row) * HD + k0]);
        float dj = d2all[j0 + row], d0j = d02all[j0 + row];
        float v0 = silu_fast(pab.x + pb4.x + dj * w256_4.x + d0j * w257_4.x);
        float v1 = silu_fast(pab.y + pb4.y + dj * w256_4.y + d0j * w257_4.y);
        float v2 = silu_fast(pab.z + pb4.z + dj * w256_4.z + d0j * w257_4.z);
        float v3 = silu_fast(pab.w + pb4.w + dj * w256_4.w + d0j * w257_4.w);
        __half h0 = __float2half_rn(v0);
        __half h1 = __float2half_rn(v1);
        __half h2 = __float2half_rn(v2);
        __half h3 = __float2half_rn(v3);
        __half2 H01 = __halves2half2(h0, h1);
        __half2 H23 = __halves2half2(h2, h3);
        __half2 L01 = __halves2half2(
            __float2half_rn(v0 - __half2float(h0)),
            __float2half_rn(v1 - __half2float(h1)));
        __half2 L23 = __halves2half2(
            __float2half_rn(v2 - __half2float(h2)),
            __float2half_rn(v3 - __half2float(h3)));
        uint32_t off = row * ROWB + lane * 8;
        asm volatile("st.shared.v2.b32 [%0], {%1, %2};"
            :: "r"(aBuf + off),
               "r"(*reinterpret_cast<uint32_t*>(&H01)),
               "r"(*reinterpret_cast<uint32_t*>(&H23)) : "memory");
        asm volatile("st.shared.v2.b32 [%0], {%1, %2};"
            :: "r"(aBuf + ATH_BYTES + off),
               "r"(*reinterpret_cast<uint32_t*>(&L01)),
               "r"(*reinterpret_cast<uint32_t*>(&L23)) : "memory");
    }
}

// warp GEMM: 2-pass fp16 split; warp tile rows mrow0..+16, cols ncol0..+32.
// pass1 = Ah x B, pass2 = Al x B.
__device__ __forceinline__ void gemm_warp(
    float acc[4][4], int mrow0, int ncol0, int lane,
    uint32_t aBuf, uint32_t bH32)
{
    uint32_t aoff, boff[2];
    {
        int arow = (lane & 15);
        int akp  = (lane >> 4) * 8;
        aoff = (mrow0 + arow) * ROWB + akp * 2;
        int bn = (lane & 7) + ((lane >> 4) & 1) * 8;
        int bkp = ((lane >> 3) & 1) * 8;
        #pragma unroll
        for (int nb = 0; nb < 2; nb++)
            boff[nb] = (ncol0 + nb * 16 + bn) * ROWB + bkp * 2;
    }
    #pragma unroll
    for (int ks = 0; ks < 8; ks++) {
        const uint32_t kb = ks * 32;
        uint32_t ah[4], al[4], bh[2][4];
        ldsm4(ah, aBuf + aoff + kb);
        ldsm4(al, aBuf + ATH_BYTES + aoff + kb);
        #pragma unroll
        for (int nb = 0; nb < 2; nb++)
            ldsm4(bh[nb], bH32 + boff[nb] + kb);
        // pass 1: Ah x B  (acc0..3)
        mma_f16(acc[0], ah, bh[0][0], bh[0][1]);
        mma_f16(acc[1], ah, bh[0][2], bh[0][3]);
        mma_f16(acc[2], ah, bh[1][0], bh[1][1]);
        mma_f16(acc[3], ah, bh[1][2], bh[1][3]);
        // pass 2: Al x B
        mma_f16(acc[0], al, bh[0][0], bh[0][1]);
        mma_f16(acc[1], al, bh[0][2], bh[0][3]);
        mma_f16(acc[2], al, bh[1][0], bh[1][1]);
        mma_f16(acc[3], al, bh[1][2], bh[1][3]);
    }
}

// ---------------- kernel 3: edge chain -> g_agg ----------------------------
// ext floats: d2all[256] d02all[256] b2s[128] eiws[128] dotP[128] e_s[32] aggW[256]
__global__ void __launch_bounds__(256, 2) edge_kernel(
    const float* __restrict__ e1w, const float* __restrict__ e1b,
    const float* __restrict__ e2b,
    const float* __restrict__ eiw, const float* __restrict__ eib)
{
    extern __shared__ __align__(16) unsigned char smem[];
    float* ext    = (float*)(smem + OFF_EXT);
    float* d2all  = ext;         float* d02all = ext + 256;
    float* b2s    = ext + 512;   float* eiws   = ext + 640;
    float* dotP   = ext + 768;   // 4*32
    float* e_s    = ext + 896;   // 32
    float* aggW   = ext + 928;   // 8*32

    const uint32_t smem32 = smem_u32(smem);
    const uint32_t bH32 = smem32 + OFF_BH;

    const int bi = blockIdx.x;
    const int b  = bi >> 8;
    const int i  = bi & 255;
    const int t  = threadIdx.x;
    const int lane = t & 31, w = t >> 5;
    const int s = lane & 3, q = lane >> 2;
    const int mrow0 = (w & 1) * 16, ncol0 = (w >> 1) * 32;

    {
        const uint4* srcH = (const uint4*)g_eBh;
        uint4* dstH = (uint4*)(smem + OFF_BH);
        for (int idx = t; idx < BT_HALF/16; idx += 256)
            dstH[idx] = srcH[idx];
    }
    if (t < 128) { b2s[t] = e2b[t]; eiws[t] = eiw[t]; }
    d2all[t]  = g_D2 [bi * NPTS + t];
    d02all[t] = g_D02[bi * NPTS + t];

    const int k0 = lane * 4;
    float4 pab = *reinterpret_cast<const float4*>(&g_PA[bi * HD + k0]);
    const float4 b1_4 = *reinterpret_cast<const float4*>(&e1b[k0]);
    pab.x += b1_4.x; pab.y += b1_4.y; pab.z += b1_4.z; pab.w += b1_4.w;
    const float4 w256_4 = *reinterpret_cast<const float4*>(&e1w[256 * HD + k0]);
    const float4 w257_4 = *reinterpret_cast<const float4*>(&e1w[257 * HD + k0]);
    const float bi0 = eib[0];
    const float* PBb = g_PB + (size_t)b * NPTS * HD;

    float aggacc[8];
    #pragma unroll
    for (int c = 0; c < 8; c++) aggacc[c] = 0.f;

    __syncthreads();
    produce_tile(w, lane, 0, pab, w256_4, w257_4, PBb, d2all, d02all, smem32);
    __syncthreads();

    for (int tile = 0; tile < 8; tile++) {
        const int j0 = tile * JT;
        const uint32_t aBuf = smem32 + (tile & 1) * ABUF_BYTES;
        // produce-ahead: next tile into other buffer (no barrier before GEMM)
        if (tile < 7)
            produce_tile(w, lane, j0 + JT, pab, w256_4, w257_4, PBb,
                         d2all, d02all, smem32 + ((tile + 1) & 1) * ABUF_BYTES);

        float acc[4][4];
        #pragma unroll
        for (int a = 0; a < 4; a++)
            #pragma unroll
            for (int e = 0; e < 4; e++) acc[a][e] = 0.f;
        gemm_warp(acc, mrow0, ncol0, lane, aBuf, bH32);

        // m = silu(D + b2); per-row dots with eiw
        float dot0 = 0.f, dot1 = 0.f;
        #pragma unroll
        for (int ni = 0; ni < 4; ni++) {
            int c0 = ncol0 + ni * 8 + 2 * s;
            float b2a = b2s[c0], b2b = b2s[c0 + 1];
            float* A = acc[ni];
            A[0] = silu_fast(A[0] + b2a); A[1] = silu_fast(A[1] + b2b);
            A[2] = silu_fast(A[2] + b2a); A[3] = silu_fast(A[3] + b2b);
            float ea = eiws[c0], eb = eiws[c0 + 1];
            dot0 += A[0]*ea + A[1]*eb;
            dot1 += A[2]*ea + A[3]*eb;
        }
        dot0 += __shfl_xor_sync(0xffffffffu, dot0, 1);
        dot0 += __shfl_xor_sync(0xffffffffu, dot0, 2);
        dot1 += __shfl_xor_sync(0xffffffffu, dot1, 1);
        dot1 += __shfl_xor_sync(0xffffffffu, dot1, 2);
        if (s == 0) {
            dotP[(w >> 1) * JT + mrow0 + q]     = dot0;
            dotP[(w >> 1) * JT + mrow0 + q + 8] = dot1;
        }
        __syncthreads();
        if (t < JT) {
            float sv = dotP[t] + dotP[JT + t] + dotP[2*JT + t]
                     + dotP[3*JT + t] + bi0;
            float e = sigm(sv);
            if (j0 + t == i) e = 0.f;
            e_s[t] = e;
        }
        __syncthreads();
        {
            float e0 = e_s[mrow0 + q], e1 = e_s[mrow0 + q + 8];
            #pragma unroll
            for (int ni = 0; ni < 4; ni++) {
                float* A = acc[ni];
                aggacc[ni*2+0] = fmaf(e0, A[0], fmaf(e1, A[2], aggacc[ni*2+0]));
                aggacc[ni*2+1] = fmaf(e0, A[1], fmaf(e1, A[3], aggacc[ni*2+1]));
            }
        }
        // no end barrier needed: next iter's dotP write is preceded by this
        // iter's sync #2, and buffer hazards are separated by >= one barrier.
    }
    // reduce aggacc over q-lanes (cols depend only on s)
    #pragma unroll
    for (int c = 0; c < 8; c++) {
        float v = aggacc[c];
        v += __shfl_xor_sync(0xffffffffu, v, 4);
        v += __shfl_xor_sync(0xffffffffu, v, 8);
        v += __shfl_xor_sync(0xffffffffu, v, 16);
        aggacc[c] = v;
    }
    __syncthreads();
    if (q == 0) {
        #pragma unroll
        for (int ni = 0; ni < 4; ni++) {
            aggW[w * 32 + ni * 8 + 2 * s]     = aggacc[ni*2+0];
            aggW[w * 32 + ni * 8 + 2 * s + 1] = aggacc[ni*2+1];
        }
    }
    __syncthreads();
    if (t < 128) {
        int cq = t >> 5, cl = t & 31;
        float sv = aggW[(2*cq) * 32 + cl] + aggW[(2*cq + 1) * 32 + cl];
        g_agg[bi * HD + t] = sv * (1.0f / 256.0f);
    }
}

// ---------------- kernel 4: coordinate chain -> g_upd ----------------------
// ext floats: d2all[256] d02all[256] b2s[128] c3ws[128] dotP[128] updx/y/z[32]
__global__ void __launch_bounds__(256, 2) cor_kernel(
    const float* __restrict__ c1w, const float* __restrict__ c1b,
    const float* __restrict__ c2b,
    const float* __restrict__ c3w, const float* __restrict__ c3b,
    const float* __restrict__ x)
{
    extern __shared__ __align__(16) unsigned char smem[];
    float* ext    = (float*)(smem + OFF_EXT);
    float* d2all  = ext;         float* d02all = ext + 256;
    float* b2s    = ext + 512;   float* c3ws   = ext + 640;
    float* dotP   = ext + 768;   // 4*32
    float* updx   = ext + 896;   float* updy = ext + 928;  float* updz = ext + 960;

    const uint32_t smem32 = smem_u32(smem);
    const uint32_t bH32 = smem32 + OFF_BH;

    const int bi = blockIdx.x;
    const int b  = bi >> 8;
    const int i  = bi & 255;
    const int t  = threadIdx.x;
    const int lane = t & 31, w = t >> 5;
    const int s = lane & 3, q = lane >> 2;
    const int mrow0 = (w & 1) * 16, ncol0 = (w >> 1) * 32;

    {
        const uint4* srcH = (const uint4*)g_cBh;
        uint4* dstH = (uint4*)(smem + OFF_BH);
        for (int idx = t; idx < BT_HALF/16; idx += 256)
            dstH[idx] = srcH[idx];
    }
    if (t < 128) { b2s[t] = c2b[t]; c3ws[t] = c3w[t]; }
    d2all[t]  = g_D2 [bi * NPTS + t];
    d02all[t] = g_D02[bi * NPTS + t];

    const int k0 = lane * 4;
    float4 pab = *reinterpret_cast<const float4*>(&g_CA[bi * HD + k0]);
    const float4 b1_4 = *reinterpret_cast<const float4*>(&c1b[k0]);
    pab.x += b1_4.x; pab.y += b1_4.y; pab.z += b1_4.z; pab.w += b1_4.w;
    const float4 w256_4 = *reinterpret_cast<const float4*>(&c1w[256 * HD + k0]);
    const float4 w257_4 = *reinterpret_cast<const float4*>(&c1w[257 * HD + k0]);
    const float b3 = c3b[0];
    const float* CBb = g_CB + (size_t)b * NPTS * HD;

    const float xi0 = x[bi * 3 + 0];
    const float xi1 = x[bi * 3 + 1];
    const float xi2 = x[bi * 3 + 2];
    float ux = 0.f, uy = 0.f, uz = 0.f;

    __syncthreads();
    produce_tile(w, lane, 0, pab, w256_4, w257_4, CBb, d2all, d02all, smem32);
    __syncthreads();

    for (int tile = 0; tile < 8; tile++) {
        const int j0 = tile * JT;
        const uint32_t aBuf = smem32 + (tile & 1) * ABUF_BYTES;
        if (tile < 7)
            produce_tile(w, lane, j0 + JT, pab, w256_4, w257_4, CBb,
                         d2all, d02all, smem32 + ((tile + 1) & 1) * ABUF_BYTES);

        float acc[4][4];
        #pragma unroll
        for (int a = 0; a < 4; a++)
            #pragma unroll
            for (int e = 0; e < 4; e++) acc[a][e] = 0.f;
        gemm_warp(acc, mrow0, ncol0, lane, aBuf, bH32);

        float dot0 = 0.f, dot1 = 0.f;
        #pragma unroll
        for (int ni = 0; ni < 4; ni++) {
            int c0 = ncol0 + ni * 8 + 2 * s;
            float b2a = b2s[c0], b2b = b2s[c0 + 1];
            float* A = acc[ni];
            float m0 = silu_fast(A[0] + b2a), m1 = silu_fast(A[1] + b2b);
            float m2 = silu_fast(A[2] + b2a), m3 = silu_fast(A[3] + b2b);
            float wa = c3ws[c0], wb = c3ws[c0 + 1];
            dot0 += m0*wa + m1*wb;
            dot1 += m2*wa + m3*wb;
        }
        dot0 += __shfl_xor_sync(0xffffffffu, dot0, 1);
        dot0 += __shfl_xor_sync(0xffffffffu, dot0, 2);
        dot1 += __shfl_xor_sync(0xffffffffu, dot1, 1);
        dot1 += __shfl_xor_sync(0xffffffffu, dot1, 2);
        if (s == 0) {
            dotP[(w >> 1) * JT + mrow0 + q]     = dot0;
            dotP[(w >> 1) * JT + mrow0 + q + 8] = dot1;
        }
        __syncthreads();
        if (t < JT) {
            int j = j0 + t;
            if (j != i) {
                float cw = dotP[t] + dotP[JT + t] + dotP[2*JT + t]
                         + dotP[3*JT + t] + b3;
                float d2v = d2all[j];
                float dist = (d2v > 0.f) ? sqrtf(d2v) : 0.f;
                float f = __fdividef(cw, dist + 1.f);
                const float* xj = x + ((size_t)b * NPTS + j) * 3;
                ux = fmaf(f, xi0 - xj[0], ux);
                uy = fmaf(f, xi1 - xj[1], uy);
                uz = fmaf(f, xi2 - xj[2], uz);
            }
        }
        __syncthreads();   // protect dotP from next iter's writes
    }
    if (t < JT) { updx[t] = ux; updy[t] = uy; updz[t] = uz; }
    __syncthreads();
    if (t < 3) {
        const float* arr = (t == 0) ? updx : (t == 1) ? updy : updz;
        float sv = 0.f;
        for (int r = 0; r < JT; r++) sv += arr[r];
        g_upd[bi * 3 + t] = sv * (1.0f / 256.0f);
    }
}

// ---------------- kernel 5: node MLP + outputs -----------------------------
__global__ void __launch_bounds__(128) final_kernel(
    const float* __restrict__ hin, const float* __restrict__ xin,
    const float* __restrict__ pm,
    const float* __restrict__ n1w, const float* __restrict__ n1b,
    const float* __restrict__ n2w, const float* __restrict__ n2b,
    float* __restrict__ out)
{
    const int r0 = blockIdx.x * 8;
    const int t  = threadIdx.x;
    __shared__ float nin[8][256];
    __shared__ float tmid[8][HD];
    #pragma unroll
    for (int r = 0; r < 8; r++) {
        nin[r][t]       = hin[(r0 + r) * HD + t];
        nin[r][HD + t]  = g_agg[(r0 + r) * HD + t];
    }
    __syncthreads();
    float a[8];
    #pragma unroll
    for (int r = 0; r < 8; r++) a[r] = n1b[t];
    for (int k = 0; k < 256; k++) {
        float wv = n1w[k * HD + t];
        #pragma unroll
        for (int r = 0; r < 8; r++) a[r] = fmaf(nin[r][k], wv, a[r]);
    }
    #pragma unroll
    for (int r = 0; r < 8; r++) tmid[r][t] = siluf(a[r]);
    __syncthreads();
    #pragma unroll
    for (int r = 0; r < 8; r++) a[r] = n2b[t];
    for (int k = 0; k < HD; k++) {
        float wv = n2w[k * HD + t];
        #pragma unroll
        for (int r = 0; r < 8; r++) a[r] = fmaf(tmid[r][k], wv, a[r]);
    }
    float* outx = out;                  // x_next: BN*3
    float* outh = out + BN * 3;         // h_next: BN*HD
    #pragma unroll
    for (int r = 0; r < 8; r++) {
        int bi = r0 + r;
        float mask = pm[bi];
        outh[bi * HD + t] = (nin[r][t] + a[r]) * mask;
        if (t < 3) outx[bi * 3 + t] = (xin[bi * 3 + t] + g_upd[bi * 3 + t]) * mask;
    }
}

// ---------------- launch ----------------------------------------------------
extern "C" void kernel_launch(void* const* d_in, const int* in_sizes, int n_in,
                              void* d_out, int out_size)
{
    const float* x   = (const float*)d_in[0];
    const float* h   = (const float*)d_in[1];
    const float* x0  = (const float*)d_in[2];
    const float* pm  = (const float*)d_in[3];
    const float* e1w = (const float*)d_in[4];
    const float* e1b = (const float*)d_in[5];
    const float* e2w = (const float*)d_in[6];
    const float* e2b = (const float*)d_in[7];
    const float* eiw = (const float*)d_in[8];
    const float* eib = (const float*)d_in[9];
    const float* n1w = (const float*)d_in[10];
    const float* n1b = (const float*)d_in[11];
    const float* n2w = (const float*)d_in[12];
    const float* n2b = (const float*)d_in[13];
    const float* c1w = (const float*)d_in[14];
    const float* c1b = (const float*)d_in[15];
    const float* c2w = (const float*)d_in[16];
    const float* c2b = (const float*)d_in[17];
    const float* c3w = (const float*)d_in[18];
    const float* c3b = (const float*)d_in[19];
    float* out = (float*)d_out;

    cudaFuncSetAttribute(edge_kernel,
        cudaFuncAttributeMaxDynamicSharedMemorySize, E_SMEM_TOTAL);
    cudaFuncSetAttribute(cor_kernel,
        cudaFuncAttributeMaxDynamicSharedMemorySize, C_SMEM_TOTAL);

    prep_kernel<<<128, 128>>>(e2w, c2w);
    proj_kernel<<<BN / 8, 128>>>(h, e1w, c1w);
    dist_kernel<<<(BN * NPTS) / 256, 256>>>(x, x0);
    edge_kernel<<<BN, 256, E_SMEM_TOTAL>>>(e1w, e1b, e2b, eiw, eib);
    cor_kernel<<<BN, 256, C_SMEM_TOTAL>>>(c1w, c1b, c2b, c3w, c3b, x);
    final_kernel<<<BN / 8, 128>>>(h, x, pm, n1w, n1b, n2w, n2b, out);
}

// round 13
// speedup vs baseline: 2.0228x; 1.2973x over previous
#include <cuda_runtime.h>
#include <cuda_fp16.h>
#include <math.h>
#include <stdint.h>

// Problem constants
#define BATCH 8
#define NPTS 256
#define HD 128
#define BN (BATCH*NPTS)          // 2048 rows
#define BSTRIDE 136              // padded row stride (fp16 elems) for ldmatrix
#define ROWB (BSTRIDE*2)         // 272 bytes per row
#define JT 32                    // j-tile rows
#define BT_HALF (128*ROWB)       // 34816 : B tile (fp16)
#define ABUF_BYTES (JT*ROWB)     // 8704 per A buffer (single fp16 tile)

// ---------------- scratch (device globals; no allocation allowed) ----------
__device__ float g_PA[BN*HD];
__device__ float g_PB[BN*HD];
__device__ float g_CA[BN*HD];
__device__ float g_CB[BN*HD];
__device__ float g_D2[BN*NPTS];
__device__ float g_D02[BN*NPTS];
__device__ float g_agg[BN*HD];
__device__ float g_upd[BN*3];
// W2^T in padded [n][k] fp16 layout (prep_kernel fills)
__device__ __align__(16) __half g_eBh[128*BSTRIDE];
__device__ __align__(16) __half g_cBh[128*BSTRIDE];

// precise sigmoid (gates only)
__device__ __forceinline__ float sigm(float v) {
    return __fdividef(1.f, 1.f + __expf(-v));
}
__device__ __forceinline__ float siluf(float v) {
    return v * sigm(v);
}
// fast silu: 1 MUFU (tanh.approx); R10 measured: no rel_err impact.
__device__ __forceinline__ float silu_fast(float v) {
    float h = 0.5f * v;
    float t;
    asm("tanh.approx.f32 %0, %1;" : "=f"(t) : "f"(h));
    return fmaf(h, t, h);
}

__device__ __forceinline__ uint32_t smem_u32(const void* p) {
    uint32_t a;
    asm("{ .reg .u64 tmp; cvta.to.shared.u64 tmp, %1; cvt.u32.u64 %0, tmp; }"
        : "=r"(a) : "l"(p));
    return a;
}

__device__ __forceinline__ void ldsm4(uint32_t r[4], uint32_t addr) {
    asm volatile("ldmatrix.sync.aligned.m8n8.x4.shared.b16 {%0,%1,%2,%3}, [%4];"
        : "=r"(r[0]), "=r"(r[1]), "=r"(r[2]), "=r"(r[3]) : "r"(addr));
}

__device__ __forceinline__ void mma_f16(float d[4], const uint32_t a[4],
                                        const uint32_t b0, const uint32_t b1) {
    asm volatile(
        "mma.sync.aligned.m16n8k16.row.col.f32.f16.f16.f32 "
        "{%0,%1,%2,%3}, {%4,%5,%6,%7}, {%8,%9}, {%0,%1,%2,%3};"
        : "+f"(d[0]), "+f"(d[1]), "+f"(d[2]), "+f"(d[3])
        : "r"(a[0]), "r"(a[1]), "r"(a[2]), "r"(a[3]), "r"(b0), "r"(b1));
}

// ---------------- kernel 0: prep W2^T fp16 padded tiles --------------------
__global__ void __launch_bounds__(128) prep_kernel(
    const float* __restrict__ e2w, const float* __restrict__ c2w)
{
    int n = blockIdx.x;
    int k = threadIdx.x;
    int idx = n * BSTRIDE + k;
    g_eBh[idx] = __float2half_rn(e2w[k * HD + n]);
    g_cBh[idx] = __float2half_rn(c2w[k * HD + n]);
}

// ---------------- kernel 1: per-node projections ---------------------------
__global__ void __launch_bounds__(128) proj_kernel(
    const float* __restrict__ h,
    const float* __restrict__ e1w,
    const float* __restrict__ c1w)
{
    const int r0 = blockIdx.x * 8;
    const int t  = threadIdx.x;
    __shared__ float hs[8][HD];
    #pragma unroll
    for (int r = 0; r < 8; r++) hs[r][t] = h[(r0 + r) * HD + t];
    __syncthreads();

    float pa[8], pb[8], ca[8], cb[8];
    #pragma unroll
    for (int r = 0; r < 8; r++) { pa[r]=0.f; pb[r]=0.f; ca[r]=0.f; cb[r]=0.f; }

    for (int k = 0; k < HD; k++) {
        float wea = e1w[k * HD + t];
        float web = e1w[(HD + k) * HD + t];
        float wca = c1w[k * HD + t];
        float wcb = c1w[(HD + k) * HD + t];
        #pragma unroll
        for (int r = 0; r < 8; r++) {
            float hk = hs[r][k];
            pa[r] = fmaf(hk, wea, pa[r]);
            pb[r] = fmaf(hk, web, pb[r]);
            ca[r] = fmaf(hk, wca, ca[r]);
            cb[r] = fmaf(hk, wcb, cb[r]);
        }
    }
    #pragma unroll
    for (int r = 0; r < 8; r++) {
        int bi = r0 + r;
        g_PA[bi * HD + t] = pa[r];
        g_PB[bi * HD + t] = pb[r];
        g_CA[bi * HD + t] = ca[r];
        g_CB[bi * HD + t] = cb[r];
    }
}

// ---------------- kernel 2: pairwise squared distances ---------------------
__global__ void __launch_bounds__(256) dist_kernel(
    const float* __restrict__ x, const float* __restrict__ x0)
{
    int idx = blockIdx.x * 256 + threadIdx.x;
    int j = idx & 255;
    int bi = idx >> 8;
    int b  = bi >> 8;
    const float* xi = x  + bi * 3;
    const float* xj = x  + (b * NPTS + j) * 3;
    float dx = xi[0]-xj[0], dy = xi[1]-xj[1], dz = xi[2]-xj[2];
    g_D2[idx] = dx*dx + dy*dy + dz*dz;
    const float* yi = x0 + bi * 3;
    const float* yj = x0 + (b * NPTS + j) * 3;
    float ex = yi[0]-yj[0], ey = yi[1]-yj[1], ez = yi[2]-yj[2];
    g_D02[idx] = ex*ex + ey*ey + ez*ez;
}

// ============================================================================
// smem layout (bytes):
//   [0      : 8704)    A buffer 0 (32 x 136 fp16)
//   [8704   : 17408)   A buffer 1
//   [17408  : 52224)   B tile (128 x 136 fp16)
//   [52224  : ...)     ext float scratch
// ============================================================================
#define OFF_BH   17408
#define OFF_EXT  52224
#define E_SMEM_TOTAL (OFF_EXT + 1184*4)
#define C_SMEM_TOTAL (OFF_EXT + 992*4)

// producer: warp w -> local rows w*4..w*4+3; lane -> k = lane*4..lane*4+3.
// plain fp16 (single precision level).
__device__ __forceinline__ void produce_tile(
    int w, int lane, int j0,
    const float4 pab, const float4 w256_4, const float4 w257_4,
    const float* __restrict__ Pbase,
    const float* d2all, const float* d02all,
    uint32_t aBuf)
{
    const int k0 = lane * 4;
    #pragma unroll
    for (int rr = 0; rr < 4; rr++) {
        int row = w * 4 + rr;
        const float4 pb4 = *reinterpret_cast<const float4*>(
            &Pbase[(size_t)(j0 + row) * HD + k0]);
        float dj = d2all[j0 + row], d0j = d02all[j0 + row];
        float v0 = silu_fast(pab.x + pb4.x + dj * w256_4.x + d0j * w257_4.x);
        float v1 = silu_fast(pab.y + pb4.y + dj * w256_4.y + d0j * w257_4.y);
        float v2 = silu_fast(pab.z + pb4.z + dj * w256_4.z + d0j * w257_4.z);
        float v3 = silu_fast(pab.w + pb4.w + dj * w256_4.w + d0j * w257_4.w);
        __half2 H01 = __floats2half2_rn(v0, v1);
        __half2 H23 = __floats2half2_rn(v2, v3);
        uint32_t off = row * ROWB + lane * 8;
        asm volatile("st.shared.v2.b32 [%0], {%1, %2};"
            :: "r"(aBuf + off),
               "r"(*reinterpret_cast<uint32_t*>(&H01)),
               "r"(*reinterpret_cast<uint32_t*>(&H23)) : "memory");
    }
}

// warp GEMM: single-pass fp16; warp tile rows mrow0..+16, cols ncol0..+32.
__device__ __forceinline__ void gemm_warp(
    float acc[4][4], int mrow0, int ncol0, int lane,
    uint32_t aBuf, uint32_t bH32)
{
    uint32_t aoff, boff[2];
    {
        int arow = (lane & 15);
        int akp  = (lane >> 4) * 8;
        aoff = (mrow0 + arow) * ROWB + akp * 2;
        int bn = (lane & 7) + ((lane >> 4) & 1) * 8;
        int bkp = ((lane >> 3) & 1) * 8;
        #pragma unroll
        for (int nb = 0; nb < 2; nb++)
            boff[nb] = (ncol0 + nb * 16 + bn) * ROWB + bkp * 2;
    }
    #pragma unroll
    for (int ks = 0; ks < 8; ks++) {
        const uint32_t kb = ks * 32;
        uint32_t ah[4], bh[2][4];
        ldsm4(ah, aBuf + aoff + kb);
        #pragma unroll
        for (int nb = 0; nb < 2; nb++)
            ldsm4(bh[nb], bH32 + boff[nb] + kb);
        mma_f16(acc[0], ah, bh[0][0], bh[0][1]);
        mma_f16(acc[1], ah, bh[0][2], bh[0][3]);
        mma_f16(acc[2], ah, bh[1][0], bh[1][1]);
        mma_f16(acc[3], ah, bh[1][2], bh[1][3]);
    }
}

// ---------------- kernel 3: edge chain -> g_agg ----------------------------
// ext floats: d2all[256] d02all[256] b2s[128] eiws[128] dotP[128] e_s[32] aggW[256]
__global__ void __launch_bounds__(256, 3) edge_kernel(
    const float* __restrict__ e1w, const float* __restrict__ e1b,
    const float* __restrict__ e2b,
    const float* __restrict__ eiw, const float* __restrict__ eib)
{
    extern __shared__ __align__(16) unsigned char smem[];
    float* ext    = (float*)(smem + OFF_EXT);
    float* d2all  = ext;         float* d02all = ext + 256;
    float* b2s    = ext + 512;   float* eiws   = ext + 640;
    float* dotP   = ext + 768;   // 4*32
    float* e_s    = ext + 896;   // 32
    float* aggW   = ext + 928;   // 8*32

    const uint32_t smem32 = smem_u32(smem);
    const uint32_t bH32 = smem32 + OFF_BH;

    const int bi = blockIdx.x;
    const int b  = bi >> 8;
    const int i  = bi & 255;
    const int t  = threadIdx.x;
    const int lane = t & 31, w = t >> 5;
    const int s = lane & 3, q = lane >> 2;
    const int mrow0 = (w & 1) * 16, ncol0 = (w >> 1) * 32;

    {
        const uint4* srcH = (const uint4*)g_eBh;
        uint4* dstH = (uint4*)(smem + OFF_BH);
        for (int idx = t; idx < BT_HALF/16; idx += 256)
            dstH[idx] = srcH[idx];
    }
    if (t < 128) { b2s[t] = e2b[t]; eiws[t] = eiw[t]; }
    d2all[t]  = g_D2 [bi * NPTS + t];
    d02all[t] = g_D02[bi * NPTS + t];

    const int k0 = lane * 4;
    float4 pab = *reinterpret_cast<const float4*>(&g_PA[bi * HD + k0]);
    const float4 b1_4 = *reinterpret_cast<const float4*>(&e1b[k0]);
    pab.x += b1_4.x; pab.y += b1_4.y; pab.z += b1_4.z; pab.w += b1_4.w;
    const float4 w256_4 = *reinterpret_cast<const float4*>(&e1w[256 * HD + k0]);
    const float4 w257_4 = *reinterpret_cast<const float4*>(&e1w[257 * HD + k0]);
    const float bi0 = eib[0];
    const float* PBb = g_PB + (size_t)b * NPTS * HD;

    float aggacc[8];
    #pragma unroll
    for (int c = 0; c < 8; c++) aggacc[c] = 0.f;

    __syncthreads();
    produce_tile(w, lane, 0, pab, w256_4, w257_4, PBb, d2all, d02all, smem32);
    __syncthreads();

    for (int tile = 0; tile < 8; tile++) {
        const int j0 = tile * JT;
        const uint32_t aBuf = smem32 + (tile & 1) * ABUF_BYTES;
        // produce-ahead: next tile into other buffer (no barrier before GEMM)
        if (tile < 7)
            produce_tile(w, lane, j0 + JT, pab, w256_4, w257_4, PBb,
                         d2all, d02all, smem32 + ((tile + 1) & 1) * ABUF_BYTES);

        float acc[4][4];
        #pragma unroll
        for (int a = 0; a < 4; a++)
            #pragma unroll
            for (int e = 0; e < 4; e++) acc[a][e] = 0.f;
        gemm_warp(acc, mrow0, ncol0, lane, aBuf, bH32);

        // m = silu(D + b2); per-row dots with eiw
        float dot0 = 0.f, dot1 = 0.f;
        #pragma unroll
        for (int ni = 0; ni < 4; ni++) {
            int c0 = ncol0 + ni * 8 + 2 * s;
            float b2a = b2s[c0], b2b = b2s[c0 + 1];
            float* A = acc[ni];
            A[0] = silu_fast(A[0] + b2a); A[1] = silu_fast(A[1] + b2b);
            A[2] = silu_fast(A[2] + b2a); A[3] = silu_fast(A[3] + b2b);
            float ea = eiws[c0], eb = eiws[c0 + 1];
            dot0 += A[0]*ea + A[1]*eb;
            dot1 += A[2]*ea + A[3]*eb;
        }
        dot0 += __shfl_xor_sync(0xffffffffu, dot0, 1);
        dot0 += __shfl_xor_sync(0xffffffffu, dot0, 2);
        dot1 += __shfl_xor_sync(0xffffffffu, dot1, 1);
        dot1 += __shfl_xor_sync(0xffffffffu, dot1, 2);
        if (s == 0) {
            dotP[(w >> 1) * JT + mrow0 + q]     = dot0;
            dotP[(w >> 1) * JT + mrow0 + q + 8] = dot1;
        }
        __syncthreads();
        if (t < JT) {
            float sv = dotP[t] + dotP[JT + t] + dotP[2*JT + t]
                     + dotP[3*JT + t] + bi0;
            float e = sigm(sv);
            if (j0 + t == i) e = 0.f;
            e_s[t] = e;
        }
        __syncthreads();
        {
            float e0 = e_s[mrow0 + q], e1 = e_s[mrow0 + q + 8];
            #pragma unroll
            for (int ni = 0; ni < 4; ni++) {
                float* A = acc[ni];
                aggacc[ni*2+0] = fmaf(e0, A[0], fmaf(e1, A[2], aggacc[ni*2+0]));
                aggacc[ni*2+1] = fmaf(e0, A[1], fmaf(e1, A[3], aggacc[ni*2+1]));
            }
        }
        // no end barrier needed: next iter's dotP write is preceded by this
        // iter's sync #2, and buffer hazards are separated by >= one barrier.
    }
    // reduce aggacc over q-lanes (cols depend only on s)
    #pragma unroll
    for (int c = 0; c < 8; c++) {
        float v = aggacc[c];
        v += __shfl_xor_sync(0xffffffffu, v, 4);
        v += __shfl_xor_sync(0xffffffffu, v, 8);
        v += __shfl_xor_sync(0xffffffffu, v, 16);
        aggacc[c] = v;
    }
    __syncthreads();
    if (q == 0) {
        #pragma unroll
        for (int ni = 0; ni < 4; ni++) {
            aggW[w * 32 + ni * 8 + 2 * s]     = aggacc[ni*2+0];
            aggW[w * 32 + ni * 8 + 2 * s + 1] = aggacc[ni*2+1];
        }
    }
    __syncthreads();
    if (t < 128) {
        int cq = t >> 5, cl = t & 31;
        float sv = aggW[(2*cq) * 32 + cl] + aggW[(2*cq + 1) * 32 + cl];
        g_agg[bi * HD + t] = sv * (1.0f / 256.0f);
    }
}

// ---------------- kernel 4: coordinate chain -> g_upd ----------------------
// ext floats: d2all[256] d02all[256] b2s[128] c3ws[128] dotP[128] updx/y/z[32]
__global__ void __launch_bounds__(256, 3) cor_kernel(
    const float* __restrict__ c1w, const float* __restrict__ c1b,
    const float* __restrict__ c2b,
    const float* __restrict__ c3w, const float* __restrict__ c3b,
    const float* __restrict__ x)
{
    extern __shared__ __align__(16) unsigned char smem[];
    float* ext    = (float*)(smem + OFF_EXT);
    float* d2all  = ext;         float* d02all = ext + 256;
    float* b2s    = ext + 512;   float* c3ws   = ext + 640;
    float* dotP   = ext + 768;   // 4*32
    float* updx   = ext + 896;   float* updy = ext + 928;  float* updz = ext + 960;

    const uint32_t smem32 = smem_u32(smem);
    const uint32_t bH32 = smem32 + OFF_BH;

    const int bi = blockIdx.x;
    const int b  = bi >> 8;
    const int i  = bi & 255;
    const int t  = threadIdx.x;
    const int lane = t & 31, w = t >> 5;
    const int s = lane & 3, q = lane >> 2;
    const int mrow0 = (w & 1) * 16, ncol0 = (w >> 1) * 32;

    {
        const uint4* srcH = (const uint4*)g_cBh;
        uint4* dstH = (uint4*)(smem + OFF_BH);
        for (int idx = t; idx < BT_HALF/16; idx += 256)
            dstH[idx] = srcH[idx];
    }
    if (t < 128) { b2s[t] = c2b[t]; c3ws[t] = c3w[t]; }
    d2all[t]  = g_D2 [bi * NPTS + t];
    d02all[t] = g_D02[bi * NPTS + t];

    const int k0 = lane * 4;
    float4 pab = *reinterpret_cast<const float4*>(&g_CA[bi * HD + k0]);
    const float4 b1_4 = *reinterpret_cast<const float4*>(&c1b[k0]);
    pab.x += b1_4.x; pab.y += b1_4.y; pab.z += b1_4.z; pab.w += b1_4.w;
    const float4 w256_4 = *reinterpret_cast<const float4*>(&c1w[256 * HD + k0]);
    const float4 w257_4 = *reinterpret_cast<const float4*>(&c1w[257 * HD + k0]);
    const float b3 = c3b[0];
    const float* CBb = g_CB + (size_t)b * NPTS * HD;

    const float xi0 = x[bi * 3 + 0];
    const float xi1 = x[bi * 3 + 1];
    const float xi2 = x[bi * 3 + 2];
    float ux = 0.f, uy = 0.f, uz = 0.f;

    __syncthreads();
    produce_tile(w, lane, 0, pab, w256_4, w257_4, CBb, d2all, d02all, smem32);
    __syncthreads();

    for (int tile = 0; tile < 8; tile++) {
        const int j0 = tile * JT;
        const uint32_t aBuf = smem32 + (tile & 1) * ABUF_BYTES;
        if (tile < 7)
            produce_tile(w, lane, j0 + JT, pab, w256_4, w257_4, CBb,
                         d2all, d02all, smem32 + ((tile + 1) & 1) * ABUF_BYTES);

        float acc[4][4];
        #pragma unroll
        for (int a = 0; a < 4; a++)
            #pragma unroll
            for (int e = 0; e < 4; e++) acc[a][e] = 0.f;
        gemm_warp(acc, mrow0, ncol0, lane, aBuf, bH32);

        float dot0 = 0.f, dot1 = 0.f;
        #pragma unroll
        for (int ni = 0; ni < 4; ni++) {
            int c0 = ncol0 + ni * 8 + 2 * s;
            float b2a = b2s[c0], b2b = b2s[c0 + 1];
            float* A = acc[ni];
            float m0 = silu_fast(A[0] + b2a), m1 = silu_fast(A[1] + b2b);
            float m2 = silu_fast(A[2] + b2a), m3 = silu_fast(A[3] + b2b);
            float wa = c3ws[c0], wb = c3ws[c0 + 1];
            dot0 += m0*wa + m1*wb;
            dot1 += m2*wa + m3*wb;
        }
        dot0 += __shfl_xor_sync(0xffffffffu, dot0, 1);
        dot0 += __shfl_xor_sync(0xffffffffu, dot0, 2);
        dot1 += __shfl_xor_sync(0xffffffffu, dot1, 1);
        dot1 += __shfl_xor_sync(0xffffffffu, dot1, 2);
        if (s == 0) {
            dotP[(w >> 1) * JT + mrow0 + q]     = dot0;
            dotP[(w >> 1) * JT + mrow0 + q + 8] = dot1;
        }
        __syncthreads();
        if (t < JT) {
            int j = j0 + t;
            if (j != i) {
                float cw = dotP[t] + dotP[JT + t] + dotP[2*JT + t]
                         + dotP[3*JT + t] + b3;
                float d2v = d2all[j];
                float dist = (d2v > 0.f) ? sqrtf(d2v) : 0.f;
                float f = __fdividef(cw, dist + 1.f);
                const float* xj = x + ((size_t)b * NPTS + j) * 3;
                ux = fmaf(f, xi0 - xj[0], ux);
                uy = fmaf(f, xi1 - xj[1], uy);
                uz = fmaf(f, xi2 - xj[2], uz);
            }
        }
        __syncthreads();   // protect dotP from next iter's writes
    }
    if (t < JT) { updx[t] = ux; updy[t] = uy; updz[t] = uz; }
    __syncthreads();
    if (t < 3) {
        const float* arr = (t == 0) ? updx : (t == 1) ? updy : updz;
        float sv = 0.f;
        for (int r = 0; r < JT; r++) sv += arr[r];
        g_upd[bi * 3 + t] = sv * (1.0f / 256.0f);
    }
}

// ---------------- kernel 5: node MLP + outputs -----------------------------
__global__ void __launch_bounds__(128) final_kernel(
    const float* __restrict__ hin, const float* __restrict__ xin,
    const float* __restrict__ pm,
    const float* __restrict__ n1w, const float* __restrict__ n1b,
    const float* __restrict__ n2w, const float* __restrict__ n2b,
    float* __restrict__ out)
{
    const int r0 = blockIdx.x * 8;
    const int t  = threadIdx.x;
    __shared__ float nin[8][256];
    __shared__ float tmid[8][HD];
    #pragma unroll
    for (int r = 0; r < 8; r++) {
        nin[r][t]       = hin[(r0 + r) * HD + t];
        nin[r][HD + t]  = g_agg[(r0 + r) * HD + t];
    }
    __syncthreads();
    float a[8];
    #pragma unroll
    for (int r = 0; r < 8; r++) a[r] = n1b[t];
    for (int k = 0; k < 256; k++) {
        float wv = n1w[k * HD + t];
        #pragma unroll
        for (int r = 0; r < 8; r++) a[r] = fmaf(nin[r][k], wv, a[r]);
    }
    #pragma unroll
    for (int r = 0; r < 8; r++) tmid[r][t] = siluf(a[r]);
    __syncthreads();
    #pragma unroll
    for (int r = 0; r < 8; r++) a[r] = n2b[t];
    for (int k = 0; k < HD; k++) {
        float wv = n2w[k * HD + t];
        #pragma unroll
        for (int r = 0; r < 8; r++) a[r] = fmaf(tmid[r][k], wv, a[r]);
    }
    float* outx = out;                  // x_next: BN*3
    float* outh = out + BN * 3;         // h_next: BN*HD
    #pragma unroll
    for (int r = 0; r < 8; r++) {
        int bi = r0 + r;
        float mask = pm[bi];
        outh[bi * HD + t] = (nin[r][t] + a[r]) * mask;
        if (t < 3) outx[bi * 3 + t] = (xin[bi * 3 + t] + g_upd[bi * 3 + t]) * mask;
    }
}

// ---------------- launch ----------------------------------------------------
extern "C" void kernel_launch(void* const* d_in, const int* in_sizes, int n_in,
                              void* d_out, int out_size)
{
    const float* x   = (const float*)d_in[0];
    const float* h   = (const float*)d_in[1];
    const float* x0  = (const float*)d_in[2];
    const float* pm  = (const float*)d_in[3];
    const float* e1w = (const float*)d_in[4];
    const float* e1b = (const float*)d_in[5];
    const float* e2w = (const float*)d_in[6];
    const float* e2b = (const float*)d_in[7];
    const float* eiw = (const float*)d_in[8];
    const float* eib = (const float*)d_in[9];
    const float* n1w = (const float*)d_in[10];
    const float* n1b = (const float*)d_in[11];
    const float* n2w = (const float*)d_in[12];
    const float* n2b = (const float*)d_in[13];
    const float* c1w = (const float*)d_in[14];
    const float* c1b = (const float*)d_in[15];
    const float* c2w = (const float*)d_in[16];
    const float* c2b = (const float*)d_in[17];
    const float* c3w = (const float*)d_in[18];
    const float* c3b = (const float*)d_in[19];
    float* out = (float*)d_out;

    cudaFuncSetAttribute(edge_kernel,
        cudaFuncAttributeMaxDynamicSharedMemorySize, E_SMEM_TOTAL);
    cudaFuncSetAttribute(cor_kernel,
        cudaFuncAttributeMaxDynamicSharedMemorySize, C_SMEM_TOTAL);

    prep_kernel<<<128, 128>>>(e2w, c2w);
    proj_kernel<<<BN / 8, 128>>>(h, e1w, c1w);
    dist_kernel<<<(BN * NPTS) / 256, 256>>>(x, x0);
    edge_kernel<<<BN, 256, E_SMEM_TOTAL>>>(e1w, e1b, e2b, eiw, eib);
    cor_kernel<<<BN, 256, C_SMEM_TOTAL>>>(c1w, c1b, c2b, c3w, c3b, x);
    final_kernel<<<BN / 8, 128>>>(h, x, pm, n1w, n1b, n2w, n2b, out);
}

// round 14
// speedup vs baseline: 2.0509x; 1.0139x over previous
#include <cuda_runtime.h>
#include <cuda_fp16.h>
#include <math.h>
#include <stdint.h>

// Problem constants
#define BATCH 8
#define NPTS 256
#define HD 128
#define BN (BATCH*NPTS)          // 2048 rows
#define BSTRIDE 136              // padded row stride (fp16 elems) for ldmatrix
#define ROWB (BSTRIDE*2)         // 272 bytes per row
#define JT 32                    // j-tile rows
#define BT_HALF (128*ROWB)       // 34816 : B tile (fp16)
#define ABUF_BYTES (JT*ROWB)     // 8704 per A buffer (single fp16 tile)

// ---------------- scratch (device globals; no allocation allowed) ----------
__device__ float g_PA[BN*HD];
__device__ float g_PB[BN*HD];
__device__ float g_CA[BN*HD];
__device__ float g_CB[BN*HD];
__device__ float g_D2[BN*NPTS];
__device__ float g_D02[BN*NPTS];
__device__ float g_agg[BN*HD];
__device__ float g_upd[BN*3];
// W2^T in padded [n][k] fp16 layout (prep_kernel fills)
__device__ __align__(16) __half g_eBh[128*BSTRIDE];
__device__ __align__(16) __half g_cBh[128*BSTRIDE];

// precise sigmoid (gates only)
__device__ __forceinline__ float sigm(float v) {
    return __fdividef(1.f, 1.f + __expf(-v));
}
__device__ __forceinline__ float siluf(float v) {
    return v * sigm(v);
}
// fast silu: 1 MUFU (tanh.approx); R10 measured: no rel_err impact.
__device__ __forceinline__ float silu_fast(float v) {
    float h = 0.5f * v;
    float t;
    asm("tanh.approx.f32 %0, %1;" : "=f"(t) : "f"(h));
    return fmaf(h, t, h);
}

__device__ __forceinline__ uint32_t smem_u32(const void* p) {
    uint32_t a;
    asm("{ .reg .u64 tmp; cvta.to.shared.u64 tmp, %1; cvt.u32.u64 %0, tmp; }"
        : "=r"(a) : "l"(p));
    return a;
}

__device__ __forceinline__ void ldsm4(uint32_t r[4], uint32_t addr) {
    asm volatile("ldmatrix.sync.aligned.m8n8.x4.shared.b16 {%0,%1,%2,%3}, [%4];"
        : "=r"(r[0]), "=r"(r[1]), "=r"(r[2]), "=r"(r[3]) : "r"(addr));
}

__device__ __forceinline__ void mma_f16(float d[4], const uint32_t a[4],
                                        const uint32_t b0, const uint32_t b1) {
    asm volatile(
        "mma.sync.aligned.m16n8k16.row.col.f32.f16.f16.f32 "
        "{%0,%1,%2,%3}, {%4,%5,%6,%7}, {%8,%9}, {%0,%1,%2,%3};"
        : "+f"(d[0]), "+f"(d[1]), "+f"(d[2]), "+f"(d[3])
        : "r"(a[0]), "r"(a[1]), "r"(a[2]), "r"(a[3]), "r"(b0), "r"(b1));
}

// ---------------- kernel 0: prep W2^T fp16 padded tiles --------------------
__global__ void __launch_bounds__(128) prep_kernel(
    const float* __restrict__ e2w, const float* __restrict__ c2w)
{
    int n = blockIdx.x;
    int k = threadIdx.x;
    int idx = n * BSTRIDE + k;
    g_eBh[idx] = __float2half_rn(e2w[k * HD + n]);
    g_cBh[idx] = __float2half_rn(c2w[k * HD + n]);
}

// ---------------- kernel 1: per-node projections ---------------------------
__global__ void __launch_bounds__(128) proj_kernel(
    const float* __restrict__ h,
    const float* __restrict__ e1w,
    const float* __restrict__ c1w)
{
    const int r0 = blockIdx.x * 8;
    const int t  = threadIdx.x;
    __shared__ float hs[8][HD];
    #pragma unroll
    for (int r = 0; r < 8; r++) hs[r][t] = h[(r0 + r) * HD + t];
    __syncthreads();

    float pa[8], pb[8], ca[8], cb[8];
    #pragma unroll
    for (int r = 0; r < 8; r++) { pa[r]=0.f; pb[r]=0.f; ca[r]=0.f; cb[r]=0.f; }

    for (int k = 0; k < HD; k++) {
        float wea = e1w[k * HD + t];
        float web = e1w[(HD + k) * HD + t];
        float wca = c1w[k * HD + t];
        float wcb = c1w[(HD + k) * HD + t];
        #pragma unroll
        for (int r = 0; r < 8; r++) {
            float hk = hs[r][k];
            pa[r] = fmaf(hk, wea, pa[r]);
            pb[r] = fmaf(hk, web, pb[r]);
            ca[r] = fmaf(hk, wca, ca[r]);
            cb[r] = fmaf(hk, wcb, cb[r]);
        }
    }
    #pragma unroll
    for (int r = 0; r < 8; r++) {
        int bi = r0 + r;
        g_PA[bi * HD + t] = pa[r];
        g_PB[bi * HD + t] = pb[r];
        g_CA[bi * HD + t] = ca[r];
        g_CB[bi * HD + t] = cb[r];
    }
}

// ---------------- kernel 2: pairwise squared distances ---------------------
__global__ void __launch_bounds__(256) dist_kernel(
    const float* __restrict__ x, const float* __restrict__ x0)
{
    int idx = blockIdx.x * 256 + threadIdx.x;
    int j = idx & 255;
    int bi = idx >> 8;
    int b  = bi >> 8;
    const float* xi = x  + bi * 3;
    const float* xj = x  + (b * NPTS + j) * 3;
    float dx = xi[0]-xj[0], dy = xi[1]-xj[1], dz = xi[2]-xj[2];
    g_D2[idx] = dx*dx + dy*dy + dz*dz;
    const float* yi = x0 + bi * 3;
    const float* yj = x0 + (b * NPTS + j) * 3;
    float ex = yi[0]-yj[0], ey = yi[1]-yj[1], ez = yi[2]-yj[2];
    g_D02[idx] = ex*ex + ey*ey + ez*ez;
}

// ============================================================================
// smem layout (bytes):
//   [0      : 8704)    A buffer 0 (32 x 136 fp16)
//   [8704   : 17408)   A buffer 1
//   [17408  : 52224)   B tile (128 x 136 fp16)  -- read once into registers
//   [52224  : ...)     ext float scratch
// ============================================================================
#define OFF_BH   17408
#define OFF_EXT  52224
#define E_SMEM_TOTAL (OFF_EXT + 1184*4)
#define C_SMEM_TOTAL (OFF_EXT + 992*4)

// producer: warp w -> local rows w*4..w*4+3; lane -> k = lane*4..lane*4+3.
__device__ __forceinline__ void produce_tile(
    int w, int lane, int j0,
    const float4 pab, const float4 w256_4, const float4 w257_4,
    const float* __restrict__ Pbase,
    const float* d2all, const float* d02all,
    uint32_t aBuf)
{
    const int k0 = lane * 4;
    #pragma unroll
    for (int rr = 0; rr < 4; rr++) {
        int row = w * 4 + rr;
        const float4 pb4 = *reinterpret_cast<const float4*>(
            &Pbase[(size_t)(j0 + row) * HD + k0]);
        float dj = d2all[j0 + row], d0j = d02all[j0 + row];
        float v0 = silu_fast(pab.x + pb4.x + dj * w256_4.x + d0j * w257_4.x);
        float v1 = silu_fast(pab.y + pb4.y + dj * w256_4.y + d0j * w257_4.y);
        float v2 = silu_fast(pab.z + pb4.z + dj * w256_4.z + d0j * w257_4.z);
        float v3 = silu_fast(pab.w + pb4.w + dj * w256_4.w + d0j * w257_4.w);
        __half2 H01 = __floats2half2_rn(v0, v1);
        __half2 H23 = __floats2half2_rn(v2, v3);
        uint32_t off = row * ROWB + lane * 8;
        asm volatile("st.shared.v2.b32 [%0], {%1, %2};"
            :: "r"(aBuf + off),
               "r"(*reinterpret_cast<uint32_t*>(&H01)),
               "r"(*reinterpret_cast<uint32_t*>(&H23)) : "memory");
    }
}

// load this warp's B fragments for all 8 k-steps into registers (64 regs)
__device__ __forceinline__ void load_B_frags(
    uint32_t bfr[8][8], int ncol0, int lane, uint32_t bH32)
{
    uint32_t boff[2];
    int bn = (lane & 7) + ((lane >> 4) & 1) * 8;
    int bkp = ((lane >> 3) & 1) * 8;
    #pragma unroll
    for (int nb = 0; nb < 2; nb++)
        boff[nb] = (ncol0 + nb * 16 + bn) * ROWB + bkp * 2;
    #pragma unroll
    for (int ks = 0; ks < 8; ks++) {
        ldsm4(&bfr[ks][0], bH32 + boff[0] + ks * 32);
        ldsm4(&bfr[ks][4], bH32 + boff[1] + ks * 32);
    }
}

// warp GEMM: single-pass fp16; A from smem, B from registers.
__device__ __forceinline__ void gemm_warp(
    float acc[4][4], const uint32_t bfr[8][8],
    int mrow0, int lane, uint32_t aBuf)
{
    const uint32_t aoff = (mrow0 + (lane & 15)) * ROWB + (lane >> 4) * 16;
    #pragma unroll
    for (int ks = 0; ks < 8; ks++) {
        uint32_t ah[4];
        ldsm4(ah, aBuf + aoff + ks * 32);
        mma_f16(acc[0], ah, bfr[ks][0], bfr[ks][1]);
        mma_f16(acc[1], ah, bfr[ks][2], bfr[ks][3]);
        mma_f16(acc[2], ah, bfr[ks][4], bfr[ks][5]);
        mma_f16(acc[3], ah, bfr[ks][6], bfr[ks][7]);
    }
}

// ---------------- kernel 3: edge chain -> g_agg ----------------------------
// ext floats: d2all[256] d02all[256] b2s[128] eiws[128] dotP[128] e_s[32] aggW[256]
__global__ void __launch_bounds__(256, 2) edge_kernel(
    const float* __restrict__ e1w, const float* __restrict__ e1b,
    const float* __restrict__ e2b,
    const float* __restrict__ eiw, const float* __restrict__ eib)
{
    extern __shared__ __align__(16) unsigned char smem[];
    float* ext    = (float*)(smem + OFF_EXT);
    float* d2all  = ext;         float* d02all = ext + 256;
    float* b2s    = ext + 512;   float* eiws   = ext + 640;
    float* dotP   = ext + 768;   // 4*32
    float* e_s    = ext + 896;   // 32
    float* aggW   = ext + 928;   // 8*32

    const uint32_t smem32 = smem_u32(smem);
    const uint32_t bH32 = smem32 + OFF_BH;

    const int bi = blockIdx.x;
    const int b  = bi >> 8;
    const int i  = bi & 255;
    const int t  = threadIdx.x;
    const int lane = t & 31, w = t >> 5;
    const int s = lane & 3, q = lane >> 2;
    const int mrow0 = (w & 1) * 16, ncol0 = (w >> 1) * 32;

    {
        const uint4* srcH = (const uint4*)g_eBh;
        uint4* dstH = (uint4*)(smem + OFF_BH);
        for (int idx = t; idx < BT_HALF/16; idx += 256)
            dstH[idx] = srcH[idx];
    }
    if (t < 128) { b2s[t] = e2b[t]; eiws[t] = eiw[t]; }
    d2all[t]  = g_D2 [bi * NPTS + t];
    d02all[t] = g_D02[bi * NPTS + t];

    const int k0 = lane * 4;
    float4 pab = *reinterpret_cast<const float4*>(&g_PA[bi * HD + k0]);
    const float4 b1_4 = *reinterpret_cast<const float4*>(&e1b[k0]);
    pab.x += b1_4.x; pab.y += b1_4.y; pab.z += b1_4.z; pab.w += b1_4.w;
    const float4 w256_4 = *reinterpret_cast<const float4*>(&e1w[256 * HD + k0]);
    const float4 w257_4 = *reinterpret_cast<const float4*>(&e1w[257 * HD + k0]);
    const float bi0 = eib[0];
    const float* PBb = g_PB + (size_t)b * NPTS * HD;

    float aggacc[8];
    #pragma unroll
    for (int c = 0; c < 8; c++) aggacc[c] = 0.f;

    __syncthreads();
    // B fragments: load once into registers (B smem never read again)
    uint32_t bfr[8][8];
    load_B_frags(bfr, ncol0, lane, bH32);
    produce_tile(w, lane, 0, pab, w256_4, w257_4, PBb, d2all, d02all, smem32);
    __syncthreads();

    for (int tile = 0; tile < 8; tile++) {
        const int j0 = tile * JT;
        const uint32_t aBuf = smem32 + (tile & 1) * ABUF_BYTES;
        // produce-ahead: next tile into other buffer (no barrier before GEMM)
        if (tile < 7)
            produce_tile(w, lane, j0 + JT, pab, w256_4, w257_4, PBb,
                         d2all, d02all, smem32 + ((tile + 1) & 1) * ABUF_BYTES);

        float acc[4][4];
        #pragma unroll
        for (int a = 0; a < 4; a++)
            #pragma unroll
            for (int e = 0; e < 4; e++) acc[a][e] = 0.f;
        gemm_warp(acc, bfr, mrow0, lane, aBuf);

        // m = silu(D + b2); per-row dots with eiw
        float dot0 = 0.f, dot1 = 0.f;
        #pragma unroll
        for (int ni = 0; ni < 4; ni++) {
            int c0 = ncol0 + ni * 8 + 2 * s;
            float b2a = b2s[c0], b2b = b2s[c0 + 1];
            float* A = acc[ni];
            A[0] = silu_fast(A[0] + b2a); A[1] = silu_fast(A[1] + b2b);
            A[2] = silu_fast(A[2] + b2a); A[3] = silu_fast(A[3] + b2b);
            float ea = eiws[c0], eb = eiws[c0 + 1];
            dot0 += A[0]*ea + A[1]*eb;
            dot1 += A[2]*ea + A[3]*eb;
        }
        dot0 += __shfl_xor_sync(0xffffffffu, dot0, 1);
        dot0 += __shfl_xor_sync(0xffffffffu, dot0, 2);
        dot1 += __shfl_xor_sync(0xffffffffu, dot1, 1);
        dot1 += __shfl_xor_sync(0xffffffffu, dot1, 2);
        if (s == 0) {
            dotP[(w >> 1) * JT + mrow0 + q]     = dot0;
            dotP[(w >> 1) * JT + mrow0 + q + 8] = dot1;
        }
        __syncthreads();
        if (t < JT) {
            float sv = dotP[t] + dotP[JT + t] + dotP[2*JT + t]
                     + dotP[3*JT + t] + bi0;
            float e = sigm(sv);
            if (j0 + t == i) e = 0.f;
            e_s[t] = e;
        }
        __syncthreads();
        {
            float e0 = e_s[mrow0 + q], e1 = e_s[mrow0 + q + 8];
            #pragma unroll
            for (int ni = 0; ni < 4; ni++) {
                float* A = acc[ni];
                aggacc[ni*2+0] = fmaf(e0, A[0], fmaf(e1, A[2], aggacc[ni*2+0]));
                aggacc[ni*2+1] = fmaf(e0, A[1], fmaf(e1, A[3], aggacc[ni*2+1]));
            }
        }
        // no end barrier needed: next iter's dotP write is preceded by this
        // iter's sync #2, and buffer hazards are separated by >= one barrier.
    }
    // reduce aggacc over q-lanes (cols depend only on s)
    #pragma unroll
    for (int c = 0; c < 8; c++) {
        float v = aggacc[c];
        v += __shfl_xor_sync(0xffffffffu, v, 4);
        v += __shfl_xor_sync(0xffffffffu, v, 8);
        v += __shfl_xor_sync(0xffffffffu, v, 16);
        aggacc[c] = v;
    }
    __syncthreads();
    if (q == 0) {
        #pragma unroll
        for (int ni = 0; ni < 4; ni++) {
            aggW[w * 32 + ni * 8 + 2 * s]     = aggacc[ni*2+0];
            aggW[w * 32 + ni * 8 + 2 * s + 1] = aggacc[ni*2+1];
        }
    }
    __syncthreads();
    if (t < 128) {
        int cq = t >> 5, cl = t & 31;
        float sv = aggW[(2*cq) * 32 + cl] + aggW[(2*cq + 1) * 32 + cl];
        g_agg[bi * HD + t] = sv * (1.0f / 256.0f);
    }
}

// ---------------- kernel 4: coordinate chain -> g_upd ----------------------
// ext floats: d2all[256] d02all[256] b2s[128] c3ws[128] dotP[128] updx/y/z[32]
__global__ void __launch_bounds__(256, 2) cor_kernel(
    const float* __restrict__ c1w, const float* __restrict__ c1b,
    const float* __restrict__ c2b,
    const float* __restrict__ c3w, const float* __restrict__ c3b,
    const float* __restrict__ x)
{
    extern __shared__ __align__(16) unsigned char smem[];
    float* ext    = (float*)(smem + OFF_EXT);
    float* d2all  = ext;         float* d02all = ext + 256;
    float* b2s    = ext + 512;   float* c3ws   = ext + 640;
    float* dotP   = ext + 768;   // 4*32
    float* updx   = ext + 896;   float* updy = ext + 928;  float* updz = ext + 960;

    const uint32_t smem32 = smem_u32(smem);
    const uint32_t bH32 = smem32 + OFF_BH;

    const int bi = blockIdx.x;
    const int b  = bi >> 8;
    const int i  = bi & 255;
    const int t  = threadIdx.x;
    const int lane = t & 31, w = t >> 5;
    const int s = lane & 3, q = lane >> 2;
    const int mrow0 = (w & 1) * 16, ncol0 = (w >> 1) * 32;

    {
        const uint4* srcH = (const uint4*)g_cBh;
        uint4* dstH = (uint4*)(smem + OFF_BH);
        for (int idx = t; idx < BT_HALF/16; idx += 256)
            dstH[idx] = srcH[idx];
    }
    if (t < 128) { b2s[t] = c2b[t]; c3ws[t] = c3w[t]; }
    d2all[t]  = g_D2 [bi * NPTS + t];
    d02all[t] = g_D02[bi * NPTS + t];

    const int k0 = lane * 4;
    float4 pab = *reinterpret_cast<const float4*>(&g_CA[bi * HD + k0]);
    const float4 b1_4 = *reinterpret_cast<const float4*>(&c1b[k0]);
    pab.x += b1_4.x; pab.y += b1_4.y; pab.z += b1_4.z; pab.w += b1_4.w;
    const float4 w256_4 = *reinterpret_cast<const float4*>(&c1w[256 * HD + k0]);
    const float4 w257_4 = *reinterpret_cast<const float4*>(&c1w[257 * HD + k0]);
    const float b3 = c3b[0];
    const float* CBb = g_CB + (size_t)b * NPTS * HD;

    const float xi0 = x[bi * 3 + 0];
    const float xi1 = x[bi * 3 + 1];
    const float xi2 = x[bi * 3 + 2];
    float ux = 0.f, uy = 0.f, uz = 0.f;

    __syncthreads();
    uint32_t bfr[8][8];
    load_B_frags(bfr, ncol0, lane, bH32);
    produce_tile(w, lane, 0, pab, w256_4, w257_4, CBb, d2all, d02all, smem32);
    __syncthreads();

    for (int tile = 0; tile < 8; tile++) {
        const int j0 = tile * JT;
        const uint32_t aBuf = smem32 + (tile & 1) * ABUF_BYTES;
        if (tile < 7)
            produce_tile(w, lane, j0 + JT, pab, w256_4, w257_4, CBb,
                         d2all, d02all, smem32 + ((tile + 1) & 1) * ABUF_BYTES);

        float acc[4][4];
        #pragma unroll
        for (int a = 0; a < 4; a++)
            #pragma unroll
            for (int e = 0; e < 4; e++) acc[a][e] = 0.f;
        gemm_warp(acc, bfr, mrow0, lane, aBuf);

        float dot0 = 0.f, dot1 = 0.f;
        #pragma unroll
        for (int ni = 0; ni < 4; ni++) {
            int c0 = ncol0 + ni * 8 + 2 * s;
            float b2a = b2s[c0], b2b = b2s[c0 + 1];
            float* A = acc[ni];
            float m0 = silu_fast(A[0] + b2a), m1 = silu_fast(A[1] + b2b);
            float m2 = silu_fast(A[2] + b2a), m3 = silu_fast(A[3] + b2b);
            float wa = c3ws[c0], wb = c3ws[c0 + 1];
            dot0 += m0*wa + m1*wb;
            dot1 += m2*wa + m3*wb;
        }
        dot0 += __shfl_xor_sync(0xffffffffu, dot0, 1);
        dot0 += __shfl_xor_sync(0xffffffffu, dot0, 2);
        dot1 += __shfl_xor_sync(0xffffffffu, dot1, 1);
        dot1 += __shfl_xor_sync(0xffffffffu, dot1, 2);
        if (s == 0) {
            dotP[(w >> 1) * JT + mrow0 + q]     = dot0;
            dotP[(w >> 1) * JT + mrow0 + q + 8] = dot1;
        }
        __syncthreads();
        if (t < JT) {
            int j = j0 + t;
            if (j != i) {
                float cw = dotP[t] + dotP[JT + t] + dotP[2*JT + t]
                         + dotP[3*JT + t] + b3;
                float d2v = d2all[j];
                float dist = (d2v > 0.f) ? sqrtf(d2v) : 0.f;
                float f = __fdividef(cw, dist + 1.f);
                const float* xj = x + ((size_t)b * NPTS + j) * 3;
                ux = fmaf(f, xi0 - xj[0], ux);
                uy = fmaf(f, xi1 - xj[1], uy);
                uz = fmaf(f, xi2 - xj[2], uz);
            }
        }
        __syncthreads();   // protect dotP from next iter's writes
    }
    if (t < JT) { updx[t] = ux; updy[t] = uy; updz[t] = uz; }
    __syncthreads();
    if (t < 3) {
        const float* arr = (t == 0) ? updx : (t == 1) ? updy : updz;
        float sv = 0.f;
        for (int r = 0; r < JT; r++) sv += arr[r];
        g_upd[bi * 3 + t] = sv * (1.0f / 256.0f);
    }
}

// ---------------- kernel 5: node MLP + outputs -----------------------------
__global__ void __launch_bounds__(128) final_kernel(
    const float* __restrict__ hin, const float* __restrict__ xin,
    const float* __restrict__ pm,
    const float* __restrict__ n1w, const float* __restrict__ n1b,
    const float* __restrict__ n2w, const float* __restrict__ n2b,
    float* __restrict__ out)
{
    const int r0 = blockIdx.x * 8;
    const int t  = threadIdx.x;
    __shared__ float nin[8][256];
    __shared__ float tmid[8][HD];
    #pragma unroll
    for (int r = 0; r < 8; r++) {
        nin[r][t]       = hin[(r0 + r) * HD + t];
        nin[r][HD + t]  = g_agg[(r0 + r) * HD + t];
    }
    __syncthreads();
    float a[8];
    #pragma unroll
    for (int r = 0; r < 8; r++) a[r] = n1b[t];
    for (int k = 0; k < 256; k++) {
        float wv = n1w[k * HD + t];
        #pragma unroll
        for (int r = 0; r < 8; r++) a[r] = fmaf(nin[r][k], wv, a[r]);
    }
    #pragma unroll
    for (int r = 0; r < 8; r++) tmid[r][t] = siluf(a[r]);
    __syncthreads();
    #pragma unroll
    for (int r = 0; r < 8; r++) a[r] = n2b[t];
    for (int k = 0; k < HD; k++) {
        float wv = n2w[k * HD + t];
        #pragma unroll
        for (int r = 0; r < 8; r++) a[r] = fmaf(tmid[r][k], wv, a[r]);
    }
    float* outx = out;                  // x_next: BN*3
    float* outh = out + BN * 3;         // h_next: BN*HD
    #pragma unroll
    for (int r = 0; r < 8; r++) {
        int bi = r0 + r;
        float mask = pm[bi];
        outh[bi * HD + t] = (nin[r][t] + a[r]) * mask;
        if (t < 3) outx[bi * 3 + t] = (xin[bi * 3 + t] + g_upd[bi * 3 + t]) * mask;
    }
}

// ---------------- launch ----------------------------------------------------
extern "C" void kernel_launch(void* const* d_in, const int* in_sizes, int n_in,
                              void* d_out, int out_size)
{
    const float* x   = (const float*)d_in[0];
    const float* h   = (const float*)d_in[1];
    const float* x0  = (const float*)d_in[2];
    const float* pm  = (const float*)d_in[3];
    const float* e1w = (const float*)d_in[4];
    const float* e1b = (const float*)d_in[5];
    const float* e2w = (const float*)d_in[6];
    const float* e2b = (const float*)d_in[7];
    const float* eiw = (const float*)d_in[8];
    const float* eib = (const float*)d_in[9];
    const float* n1w = (const float*)d_in[10];
    const float* n1b = (const float*)d_in[11];
    const float* n2w = (const float*)d_in[12];
    const float* n2b = (const float*)d_in[13];
    const float* c1w = (const float*)d_in[14];
    const float* c1b = (const float*)d_in[15];
    const float* c2w = (const float*)d_in[16];
    const float* c2b = (const float*)d_in[17];
    const float* c3w = (const float*)d_in[18];
    const float* c3b = (const float*)d_in[19];
    float* out = (float*)d_out;

    cudaFuncSetAttribute(edge_kernel,
        cudaFuncAttributeMaxDynamicSharedMemorySize, E_SMEM_TOTAL);
    cudaFuncSetAttribute(cor_kernel,
        cudaFuncAttributeMaxDynamicSharedMemorySize, C_SMEM_TOTAL);

    prep_kernel<<<128, 128>>>(e2w, c2w);
    proj_kernel<<<BN / 8, 128>>>(h, e1w, c1w);
    dist_kernel<<<(BN * NPTS) / 256, 256>>>(x, x0);
    edge_kernel<<<BN, 256, E_SMEM_TOTAL>>>(e1w, e1b, e2b, eiw, eib);
    cor_kernel<<<BN, 256, C_SMEM_TOTAL>>>(c1w, c1b, c2b, c3w, c3b, x);
    final_kernel<<<BN / 8, 128>>>(h, x, pm, n1w, n1b, n2w, n2b, out);
}